// round 3
// baseline (speedup 1.0000x reference)
#include <cuda_runtime.h>
#include <math.h>

#define Nn 20000
#define Ee 320000
#define Ff 128
#define Hh 256
#define EPS 1e-5f

// ---- device scratch (no allocations allowed) ----
__device__ float d_C[512 * 128];      // folded layer-1 weights: [0:256)=A(dst), [256:512)=B(src)
__device__ float d_W2f[256 * 256];    // folded layer-2 weights
__device__ float d_b1f[256];
__device__ float d_b2f[256];
__device__ float d_UV[(size_t)Nn * 512];   // per-node u (cols 0..255) and v (cols 256..511)
__device__ float d_sum[(size_t)Nn * Ff];   // scatter-sum accumulator
__device__ float d_cnt[Nn];                // degree

// ---------------------------------------------------------------
__global__ void zero_kernel() {
    int i = blockIdx.x * blockDim.x + threadIdx.x;
    if (i < Nn * Ff) d_sum[i] = 0.0f;
    if (i < Nn)      d_cnt[i] = 0.0f;
}

// Fold BN into weights/bias; build C = [s1*(W1_L - W1_R); s1*W1_R]
__global__ void prep_kernel(const float* __restrict__ W1, const float* __restrict__ b1,
                            const float* __restrict__ g1, const float* __restrict__ be1,
                            const float* __restrict__ rm1, const float* __restrict__ rv1,
                            const float* __restrict__ W2, const float* __restrict__ b2,
                            const float* __restrict__ g2, const float* __restrict__ be2,
                            const float* __restrict__ rm2, const float* __restrict__ rv2) {
    int i = blockIdx.x * blockDim.x + threadIdx.x;
    if (i < 512 * 128) {
        int j = i >> 7;            // 0..511
        int k = i & 127;
        int o = j & 255;
        float s = g1[o] * rsqrtf(rv1[o] + EPS);
        float w = (j < 256) ? (W1[o * 256 + k] - W1[o * 256 + 128 + k])
                            : W1[o * 256 + 128 + k];
        d_C[i] = s * w;
    }
    if (i < 256 * 256) {
        int o = i >> 8;
        float s = g2[o] * rsqrtf(rv2[o] + EPS);
        d_W2f[i] = s * W2[i];
    }
    if (i < 256) {
        float s1v = g1[i] * rsqrtf(rv1[i] + EPS);
        d_b1f[i] = b1[i] * s1v + (be1[i] - rm1[i] * s1v);
        float s2v = g2[i] * rsqrtf(rv2[i] + EPS);
        d_b2f[i] = b2[i] * s2v + (be2[i] - rm2[i] * s2v);
    }
}

// UV = x @ C^T   ([20000,128] @ [128,512]) — node-level layer-1 projection
#define UVSMEM (2 * 64 * 129 * 4)
__global__ void uv_gemm(const float* __restrict__ x) {
    extern __shared__ float sm[];
    float* xs = sm;                 // [64][129]
    float* cs = sm + 64 * 129;      // [64][129]
    int t = threadIdx.x, tx = t & 15, ty = t >> 4;
    int rowBase = blockIdx.x * 64;
    int colBase = blockIdx.y * 64;

    for (int i = t; i < 64 * 128; i += 256) {
        int r = i >> 7, c = i & 127;
        int gr = rowBase + r;
        xs[r * 129 + c] = (gr < Nn) ? x[(size_t)gr * 128 + c] : 0.0f;
    }
    for (int i = t; i < 64 * 128; i += 256) {
        int r = i >> 7, c = i & 127;
        cs[r * 129 + c] = d_C[(colBase + r) * 128 + c];
    }
    __syncthreads();

    float acc[4][4] = {};
    int r0 = ty * 4, c0 = tx * 4;
#pragma unroll 8
    for (int k = 0; k < 128; ++k) {
        float a[4], b[4];
#pragma unroll
        for (int i = 0; i < 4; ++i) a[i] = xs[(r0 + i) * 129 + k];
#pragma unroll
        for (int j = 0; j < 4; ++j) b[j] = cs[(c0 + j) * 129 + k];
#pragma unroll
        for (int i = 0; i < 4; ++i)
#pragma unroll
            for (int j = 0; j < 4; ++j) acc[i][j] += a[i] * b[j];
    }
#pragma unroll
    for (int i = 0; i < 4; ++i) {
        int gr = rowBase + r0 + i;
        if (gr < Nn) {
#pragma unroll
            for (int j = 0; j < 4; ++j)
                d_UV[(size_t)gr * 512 + colBase + c0 + j] = acc[i][j];
        }
    }
}

// edge_index is int32 on the wire (JAX default config has x64 disabled, so
// jnp.int64 silently materializes as int32). src = ei[i], dst = ei[E + i].
__global__ void degree_kernel(const int* __restrict__ ei) {
    int i = blockIdx.x * blockDim.x + threadIdx.x;
    if (i < Ee) atomicAdd(&d_cnt[ei[Ee + i]], 1.0f);
}

// Fused per-edge MLP: h1 = relu(u[dst]+v[src]+b1f); h2 = relu(h1@W2f^T+b2f);
// h3 = h2@W3^T+b3; atomicAdd into d_sum[dst].
#define EDGESMEM (3 * 64 * 257 * 4)
__global__ void edge_kernel(const int* __restrict__ ei,
                            const float* __restrict__ W3,
                            const float* __restrict__ b3) {
    extern __shared__ float sm[];
    float* hin  = sm;                    // [64][257] (256 used)
    float* wt   = sm + 64 * 257;         // [64][257]
    float* hout = sm + 2 * 64 * 257;     // [64][257]
    __shared__ int s_src[64], s_dst[64];

    int t = threadIdx.x, tx = t & 15, ty = t >> 4;
    int e0 = blockIdx.x * 64;

    if (t < 64)        s_src[t]      = ei[e0 + t];
    else if (t < 128)  s_dst[t - 64] = ei[Ee + e0 + (t - 64)];
    __syncthreads();

    // ---- phase 1: layer-1 (gather + add + relu), one column per thread ----
    {
        float b1v = d_b1f[t];
#pragma unroll 4
        for (int e = 0; e < 64; ++e) {
            const float* ud = d_UV + (size_t)s_dst[e] * 512;
            const float* vs = d_UV + (size_t)s_src[e] * 512 + 256;
            float v = ud[t] + vs[t] + b1v;
            hin[e * 257 + t] = fmaxf(v, 0.0f);
        }
    }
    __syncthreads();

    int r0 = ty * 4, c0 = tx * 4;

    // ---- phase 2: layer-2 GEMM (M=64 edges, N=256 in 4 chunks, K=256) ----
    for (int nc = 0; nc < 4; ++nc) {
        for (int i = t; i < 64 * 256; i += 256) {
            int r = i >> 8, c = i & 255;
            wt[r * 257 + c] = d_W2f[(nc * 64 + r) * 256 + c];
        }
        __syncthreads();

        float acc[4][4] = {};
#pragma unroll 8
        for (int k = 0; k < 256; ++k) {
            float a[4], b[4];
#pragma unroll
            for (int i = 0; i < 4; ++i) a[i] = hin[(r0 + i) * 257 + k];
#pragma unroll
            for (int j = 0; j < 4; ++j) b[j] = wt[(c0 + j) * 257 + k];
#pragma unroll
            for (int i = 0; i < 4; ++i)
#pragma unroll
                for (int j = 0; j < 4; ++j) acc[i][j] += a[i] * b[j];
        }
        __syncthreads();   // wt fully consumed before next chunk overwrites it

#pragma unroll
        for (int i = 0; i < 4; ++i)
#pragma unroll
            for (int j = 0; j < 4; ++j) {
                int oc = nc * 64 + c0 + j;
                hout[(r0 + i) * 257 + oc] = fmaxf(acc[i][j] + d_b2f[oc], 0.0f);
            }
        __syncthreads();
    }

    // ---- phase 3: layer-3 GEMM (N=128 in 2 chunks, K=256) + scatter ----
    for (int nc = 0; nc < 2; ++nc) {
        for (int i = t; i < 64 * 256; i += 256) {
            int r = i >> 8, c = i & 255;
            wt[r * 257 + c] = W3[(nc * 64 + r) * 256 + c];
        }
        __syncthreads();

        float acc[4][4] = {};
#pragma unroll 8
        for (int k = 0; k < 256; ++k) {
            float a[4], b[4];
#pragma unroll
            for (int i = 0; i < 4; ++i) a[i] = hout[(r0 + i) * 257 + k];
#pragma unroll
            for (int j = 0; j < 4; ++j) b[j] = wt[(c0 + j) * 257 + k];
#pragma unroll
            for (int i = 0; i < 4; ++i)
#pragma unroll
                for (int j = 0; j < 4; ++j) acc[i][j] += a[i] * b[j];
        }
        __syncthreads();

#pragma unroll
        for (int i = 0; i < 4; ++i) {
            int dn = s_dst[r0 + i];
#pragma unroll
            for (int j = 0; j < 4; ++j) {
                int oc = nc * 64 + c0 + j;
                atomicAdd(&d_sum[(size_t)dn * Ff + oc], acc[i][j] + b3[oc]);
            }
        }
    }
}

__global__ void final_kernel(float* __restrict__ out) {
    int i = blockIdx.x * blockDim.x + threadIdx.x;
    if (i < Nn * Ff) {
        int n = i >> 7;
        float c = fmaxf(d_cnt[n], 1.0f);
        out[i] = tanhf(d_sum[i] / c);
    }
}

// ---------------------------------------------------------------
extern "C" void kernel_launch(void* const* d_in, const int* in_sizes, int n_in,
                              void* d_out, int out_size) {
    const float* x  = (const float*)d_in[0];
    const int*   ei = (const int*)d_in[1];     // int32! (JAX x64 disabled)
    const float* W1 = (const float*)d_in[2];
    const float* b1 = (const float*)d_in[3];
    const float* g1 = (const float*)d_in[4];
    const float* be1 = (const float*)d_in[5];
    const float* rm1 = (const float*)d_in[6];
    const float* rv1 = (const float*)d_in[7];
    const float* W2 = (const float*)d_in[8];
    const float* b2 = (const float*)d_in[9];
    const float* g2 = (const float*)d_in[10];
    const float* be2 = (const float*)d_in[11];
    const float* rm2 = (const float*)d_in[12];
    const float* rv2 = (const float*)d_in[13];
    const float* W3 = (const float*)d_in[14];
    const float* b3 = (const float*)d_in[15];
    float* out = (float*)d_out;

    cudaFuncSetAttribute(uv_gemm, cudaFuncAttributeMaxDynamicSharedMemorySize, UVSMEM);
    cudaFuncSetAttribute(edge_kernel, cudaFuncAttributeMaxDynamicSharedMemorySize, EDGESMEM);

    zero_kernel<<<(Nn * Ff + 255) / 256, 256>>>();
    prep_kernel<<<(512 * 128 + 255) / 256, 256>>>(W1, b1, g1, be1, rm1, rv1,
                                                  W2, b2, g2, be2, rm2, rv2);
    uv_gemm<<<dim3((Nn + 63) / 64, 8), 256, UVSMEM>>>(x);
    degree_kernel<<<(Ee + 255) / 256, 256>>>(ei);
    edge_kernel<<<Ee / 64, 256, EDGESMEM>>>(ei, W3, b3);
    final_kernel<<<(Nn * Ff + 255) / 256, 256>>>(out);
}

// round 4
// speedup vs baseline: 2.6665x; 2.6665x over previous
#include <cuda_runtime.h>
#include <math.h>
#include <stdint.h>

#define Nn 20000
#define Ee 320000
#define Ff 128
#define Hh 256
#define EPS 1e-5f

#define SA 260   // hin stride (words); 260 % 32 == 4 -> conflict-free fragment LDS
#define SB 68    // weight-tile stride; 68 % 32 == 4

// ---- device scratch ----
__device__ float d_C[512 * 128];      // folded layer-1 weights (tf32-rounded)
__device__ float d_W2f[256 * 256];    // folded layer-2 weights (tf32-rounded)
__device__ float d_W3r[128 * 256];    // layer-3 weights (tf32-rounded)
__device__ float d_b1f[256];
__device__ float d_b2f[256];
__device__ float d_UV[(size_t)Nn * 512];   // u (cols 0..255), v (cols 256..511)
__device__ float d_sum[(size_t)Nn * Ff];
__device__ float d_cnt[Nn];

__device__ __forceinline__ float tf32r(float x) {
    uint32_t u;
    asm("cvt.rna.tf32.f32 %0, %1;" : "=r"(u) : "f"(x));
    return __uint_as_float(u);
}

__device__ __forceinline__ void mma8(float d[4], const uint32_t a[4], const uint32_t b[2]) {
    asm volatile(
        "mma.sync.aligned.m16n8k8.row.col.f32.tf32.tf32.f32 "
        "{%0,%1,%2,%3}, {%4,%5,%6,%7}, {%8,%9}, {%0,%1,%2,%3};\n"
        : "+f"(d[0]), "+f"(d[1]), "+f"(d[2]), "+f"(d[3])
        : "r"(a[0]), "r"(a[1]), "r"(a[2]), "r"(a[3]), "r"(b[0]), "r"(b[1]));
}

// ---------------------------------------------------------------
__global__ void zero_kernel() {
    int i = blockIdx.x * blockDim.x + threadIdx.x;
    if (i < Nn * Ff) d_sum[i] = 0.0f;
    if (i < Nn)      d_cnt[i] = 0.0f;
}

__global__ void prep_kernel(const float* __restrict__ W1, const float* __restrict__ b1,
                            const float* __restrict__ g1, const float* __restrict__ be1,
                            const float* __restrict__ rm1, const float* __restrict__ rv1,
                            const float* __restrict__ W2, const float* __restrict__ b2,
                            const float* __restrict__ g2, const float* __restrict__ be2,
                            const float* __restrict__ rm2, const float* __restrict__ rv2,
                            const float* __restrict__ W3) {
    int i = blockIdx.x * blockDim.x + threadIdx.x;
    if (i < 512 * 128) {
        int j = i >> 7, k = i & 127, o = j & 255;
        float s = g1[o] * rsqrtf(rv1[o] + EPS);
        float w = (j < 256) ? (W1[o * 256 + k] - W1[o * 256 + 128 + k])
                            : W1[o * 256 + 128 + k];
        d_C[i] = tf32r(s * w);
    }
    if (i < 256 * 256) {
        int o = i >> 8;
        float s = g2[o] * rsqrtf(rv2[o] + EPS);
        d_W2f[i] = tf32r(s * W2[i]);
    }
    if (i < 128 * 256) d_W3r[i] = tf32r(W3[i]);
    if (i < 256) {
        float s1v = g1[i] * rsqrtf(rv1[i] + EPS);
        d_b1f[i] = b1[i] * s1v + (be1[i] - rm1[i] * s1v);
        float s2v = g2[i] * rsqrtf(rv2[i] + EPS);
        d_b2f[i] = b2[i] * s2v + (be2[i] - rm2[i] * s2v);
    }
}

// UV = x @ C^T  via tf32 mma. Block tile: 64 nodes x 256 C-rows. grid (313, 2).
#define SXU 132   // 132 % 32 == 4
#define UVSMEM ((64 + 256) * SXU * 4)
__global__ __launch_bounds__(256, 1) void uv_gemm(const float* __restrict__ x) {
    extern __shared__ float sm[];
    float* xs = sm;                // [64][SXU]
    float* cs = sm + 64 * SXU;     // [256][SXU]
    int t = threadIdx.x, lane = t & 31, wid = t >> 5;
    int rowBase = blockIdx.x * 64;
    int cb = blockIdx.y * 256;

    // stage x tile (cvt to tf32), 8 float4 per thread
#pragma unroll
    for (int j = 0; j < 8; ++j) {
        int idx = t + j * 256;            // 0..2047
        int r = idx >> 5, c4 = idx & 31;
        int gr = rowBase + r;
        float4 v = (gr < Nn) ? *(const float4*)(x + (size_t)gr * 128 + c4 * 4)
                             : make_float4(0.f, 0.f, 0.f, 0.f);
        float4 w = make_float4(tf32r(v.x), tf32r(v.y), tf32r(v.z), tf32r(v.w));
        *(float4*)(xs + r * SXU + c4 * 4) = w;
    }
    // stage C tile (already rounded), 32 float4 per thread
#pragma unroll
    for (int j = 0; j < 32; ++j) {
        int idx = t + j * 256;            // 0..8191
        int n = idx >> 5, c4 = idx & 31;
        float4 v = *(const float4*)(d_C + (size_t)(cb + n) * 128 + c4 * 4);
        *(float4*)(cs + n * SXU + c4 * 4) = v;
    }
    __syncthreads();

    int warpM = wid >> 2, warpN = wid & 3;
    int rB = warpM * 32, cB = warpN * 64;
    int qr = lane >> 2, qc = lane & 3;

    float acc[2][8][4] = {};
#pragma unroll
    for (int ks = 0; ks < 16; ++ks) {
        int kk = ks * 8;
        uint32_t a[2][4];
#pragma unroll
        for (int mi = 0; mi < 2; ++mi) {
            int r0 = rB + mi * 16 + qr;
            a[mi][0] = __float_as_uint(xs[r0 * SXU + kk + qc]);
            a[mi][1] = __float_as_uint(xs[(r0 + 8) * SXU + kk + qc]);
            a[mi][2] = __float_as_uint(xs[r0 * SXU + kk + qc + 4]);
            a[mi][3] = __float_as_uint(xs[(r0 + 8) * SXU + kk + qc + 4]);
        }
#pragma unroll
        for (int ni = 0; ni < 8; ++ni) {
            int n0 = cB + ni * 8 + qr;
            uint32_t b[2];
            b[0] = __float_as_uint(cs[n0 * SXU + kk + qc]);
            b[1] = __float_as_uint(cs[n0 * SXU + kk + qc + 4]);
            mma8(acc[0][ni], a[0], b);
            mma8(acc[1][ni], a[1], b);
        }
    }
    // write UV
#pragma unroll
    for (int mi = 0; mi < 2; ++mi)
#pragma unroll
        for (int ni = 0; ni < 8; ++ni) {
            int r0 = rowBase + rB + mi * 16 + qr;
            int c0 = cb + cB + ni * 8 + 2 * qc;
            if (r0 < Nn)
                *(float2*)(d_UV + (size_t)r0 * 512 + c0) =
                    make_float2(acc[mi][ni][0], acc[mi][ni][1]);
            if (r0 + 8 < Nn)
                *(float2*)(d_UV + (size_t)(r0 + 8) * 512 + c0) =
                    make_float2(acc[mi][ni][2], acc[mi][ni][3]);
        }
}

// edge_index is int32 on the wire (JAX x64 disabled). src=ei[i], dst=ei[E+i].
__global__ void degree_kernel(const int* __restrict__ ei) {
    int i = blockIdx.x * blockDim.x + threadIdx.x;
    if (i < Ee) atomicAdd(&d_cnt[ei[Ee + i]], 1.0f);
}

// Fused per-edge MLP on tensor cores. 64 edges/block, 8 warps.
#define EDGESMEM ((64 * SA + 256 * SB) * 4)
__global__ __launch_bounds__(256, 1) void edge_kernel(const int* __restrict__ ei,
                                                      const float* __restrict__ b3) {
    extern __shared__ float sm[];
    float* hin = sm;               // [64][SA]  (layer-1 out, then layer-2 out)
    float* wt  = sm + 64 * SA;     // [256][SB] weight k-slices
    __shared__ int s_src[64], s_dst[64];
    __shared__ float s_b2[256], s_b3[128];

    int t = threadIdx.x, lane = t & 31, wid = t >> 5;
    int e0 = blockIdx.x * 64;

    if (t < 64)                 s_src[t] = ei[e0 + t];
    else if (t < 128)           s_dst[t - 64] = ei[Ee + e0 + (t - 64)];
    s_b2[t] = d_b2f[t];
    if (t < 128) s_b3[t] = b3[t];
    __syncthreads();

    // ---- phase 1: layer-1 gather + relu -> hin (tf32) ----
    {
        float b1v = d_b1f[t];
#pragma unroll 4
        for (int e = 0; e < 64; ++e) {
            float v = d_UV[(size_t)s_dst[e] * 512 + t]
                    + d_UV[(size_t)s_src[e] * 512 + 256 + t] + b1v;
            hin[e * SA + t] = tf32r(fmaxf(v, 0.0f));
        }
    }

    int warpM = wid >> 2, warpN = wid & 3;
    int rB = warpM * 32;
    int qr = lane >> 2, qc = lane & 3;

    // ---- layer 2: [64,256] = hin[64,256] @ W2f^T, warp tile 32x64 ----
    float acc[2][8][4] = {};
    {
        int cB = warpN * 64;
        for (int kc = 0; kc < 4; ++kc) {
            __syncthreads();   // wt free (prev mma done) / hin writes visible
#pragma unroll
            for (int j = 0; j < 16; ++j) {       // stage wt[256][64]
                int idx = t + j * 256;           // 0..4095
                int n = idx >> 4, k4 = idx & 15;
                float4 w = *(const float4*)(d_W2f + (size_t)n * 256 + kc * 64 + k4 * 4);
                *(float4*)(wt + n * SB + k4 * 4) = w;
            }
            __syncthreads();
#pragma unroll
            for (int ks = 0; ks < 8; ++ks) {
                int kk = ks * 8;
                int kg = kc * 64 + kk;
                uint32_t a[2][4];
#pragma unroll
                for (int mi = 0; mi < 2; ++mi) {
                    int r0 = rB + mi * 16 + qr;
                    a[mi][0] = __float_as_uint(hin[r0 * SA + kg + qc]);
                    a[mi][1] = __float_as_uint(hin[(r0 + 8) * SA + kg + qc]);
                    a[mi][2] = __float_as_uint(hin[r0 * SA + kg + qc + 4]);
                    a[mi][3] = __float_as_uint(hin[(r0 + 8) * SA + kg + qc + 4]);
                }
#pragma unroll
                for (int ni = 0; ni < 8; ++ni) {
                    int n0 = cB + ni * 8 + qr;
                    uint32_t b[2];
                    b[0] = __float_as_uint(wt[n0 * SB + kk + qc]);
                    b[1] = __float_as_uint(wt[n0 * SB + kk + qc + 4]);
                    mma8(acc[0][ni], a[0], b);
                    mma8(acc[1][ni], a[1], b);
                }
            }
        }
        __syncthreads();   // all layer-2 reads of hin done
        // bias + relu + tf32, write back over hin
#pragma unroll
        for (int mi = 0; mi < 2; ++mi)
#pragma unroll
            for (int ni = 0; ni < 8; ++ni) {
                int r0 = rB + mi * 16 + qr;
                int c0 = cB + ni * 8 + 2 * qc;
                hin[r0 * SA + c0]       = tf32r(fmaxf(acc[mi][ni][0] + s_b2[c0], 0.f));
                hin[r0 * SA + c0 + 1]   = tf32r(fmaxf(acc[mi][ni][1] + s_b2[c0 + 1], 0.f));
                hin[(r0 + 8) * SA + c0]     = tf32r(fmaxf(acc[mi][ni][2] + s_b2[c0], 0.f));
                hin[(r0 + 8) * SA + c0 + 1] = tf32r(fmaxf(acc[mi][ni][3] + s_b2[c0 + 1], 0.f));
            }
    }

    // ---- layer 3: [64,128] = h2[64,256] @ W3^T, warp tile 32x32 ----
    float acc3[2][4][4] = {};
    {
        int cB = warpN * 32;
        for (int kc = 0; kc < 4; ++kc) {
            __syncthreads();   // wt free; (kc==0) h2 writes visible after this+stage sync
#pragma unroll
            for (int j = 0; j < 8; ++j) {        // stage wt[128][64]
                int idx = t + j * 256;           // 0..2047
                int n = idx >> 4, k4 = idx & 15;
                float4 w = *(const float4*)(d_W3r + (size_t)n * 256 + kc * 64 + k4 * 4);
                *(float4*)(wt + n * SB + k4 * 4) = w;
            }
            __syncthreads();
#pragma unroll
            for (int ks = 0; ks < 8; ++ks) {
                int kk = ks * 8;
                int kg = kc * 64 + kk;
                uint32_t a[2][4];
#pragma unroll
                for (int mi = 0; mi < 2; ++mi) {
                    int r0 = rB + mi * 16 + qr;
                    a[mi][0] = __float_as_uint(hin[r0 * SA + kg + qc]);
                    a[mi][1] = __float_as_uint(hin[(r0 + 8) * SA + kg + qc]);
                    a[mi][2] = __float_as_uint(hin[r0 * SA + kg + qc + 4]);
                    a[mi][3] = __float_as_uint(hin[(r0 + 8) * SA + kg + qc + 4]);
                }
#pragma unroll
                for (int ni = 0; ni < 4; ++ni) {
                    int n0 = cB + ni * 8 + qr;
                    uint32_t b[2];
                    b[0] = __float_as_uint(wt[n0 * SB + kk + qc]);
                    b[1] = __float_as_uint(wt[n0 * SB + kk + qc + 4]);
                    mma8(acc3[0][ni], a[0], b);
                    mma8(acc3[1][ni], a[1], b);
                }
            }
        }
        // scatter: bias + vector atomic into d_sum[dst]
#pragma unroll
        for (int mi = 0; mi < 2; ++mi)
#pragma unroll
            for (int ni = 0; ni < 4; ++ni) {
                int r0 = rB + mi * 16 + qr;
                int c0 = cB + ni * 8 + 2 * qc;
                float bx = s_b3[c0], by = s_b3[c0 + 1];
                float* p0 = d_sum + (size_t)s_dst[r0] * Ff + c0;
                float* p1 = d_sum + (size_t)s_dst[r0 + 8] * Ff + c0;
                asm volatile("red.global.add.v2.f32 [%0], {%1,%2};"
                             :: "l"(p0), "f"(acc3[mi][ni][0] + bx), "f"(acc3[mi][ni][1] + by)
                             : "memory");
                asm volatile("red.global.add.v2.f32 [%0], {%1,%2};"
                             :: "l"(p1), "f"(acc3[mi][ni][2] + bx), "f"(acc3[mi][ni][3] + by)
                             : "memory");
            }
    }
}

__global__ void final_kernel(float* __restrict__ out) {
    int i = blockIdx.x * blockDim.x + threadIdx.x;
    if (i < Nn * Ff) {
        int n = i >> 7;
        float c = fmaxf(d_cnt[n], 1.0f);
        out[i] = tanhf(d_sum[i] / c);
    }
}

// ---------------------------------------------------------------
extern "C" void kernel_launch(void* const* d_in, const int* in_sizes, int n_in,
                              void* d_out, int out_size) {
    const float* x  = (const float*)d_in[0];
    const int*   ei = (const int*)d_in[1];     // int32 (JAX x64 disabled)
    const float* W1 = (const float*)d_in[2];
    const float* b1 = (const float*)d_in[3];
    const float* g1 = (const float*)d_in[4];
    const float* be1 = (const float*)d_in[5];
    const float* rm1 = (const float*)d_in[6];
    const float* rv1 = (const float*)d_in[7];
    const float* W2 = (const float*)d_in[8];
    const float* b2 = (const float*)d_in[9];
    const float* g2 = (const float*)d_in[10];
    const float* be2 = (const float*)d_in[11];
    const float* rm2 = (const float*)d_in[12];
    const float* rv2 = (const float*)d_in[13];
    const float* W3 = (const float*)d_in[14];
    const float* b3 = (const float*)d_in[15];
    float* out = (float*)d_out;

    cudaFuncSetAttribute(uv_gemm, cudaFuncAttributeMaxDynamicSharedMemorySize, UVSMEM);
    cudaFuncSetAttribute(edge_kernel, cudaFuncAttributeMaxDynamicSharedMemorySize, EDGESMEM);

    zero_kernel<<<(Nn * Ff + 255) / 256, 256>>>();
    prep_kernel<<<(512 * 128 + 255) / 256, 256>>>(W1, b1, g1, be1, rm1, rv1,
                                                  W2, b2, g2, be2, rm2, rv2, W3);
    uv_gemm<<<dim3((Nn + 63) / 64, 2), 256, UVSMEM>>>(x);
    degree_kernel<<<(Ee + 255) / 256, 256>>>(ei);
    edge_kernel<<<Ee / 64, 256, EDGESMEM>>>(ei, b3);
    final_kernel<<<(Nn * Ff + 255) / 256, 256>>>(out);
}

// round 5
// speedup vs baseline: 3.8476x; 1.4429x over previous
#include <cuda_runtime.h>
#include <math.h>
#include <stdint.h>

#define Nn 20000
#define Ee 320000
#define Ff 128
#define EPS 1e-5f

#define EPB 128          // edges per block
#define THREADS 512
#define SA 260           // hin stride (words); 260 % 32 == 4 -> conflict-free fragment LDS
#define SB 68            // weight-tile stride; 68 % 32 == 4

// ---- device scratch ----
__device__ float d_C[512 * 128];      // folded layer-1 weights (tf32-rounded)
__device__ float d_W2f[256 * 256];    // folded layer-2 weights (tf32-rounded)
__device__ float d_W3r[128 * 256];    // layer-3 weights (tf32-rounded)
__device__ float d_b1f[256];
__device__ float d_b2f[256];
__device__ float d_UV[(size_t)Nn * 512];   // u (cols 0..255), v (cols 256..511)
__device__ float d_sum[(size_t)Nn * Ff];
__device__ float d_cnt[Nn];

__device__ __forceinline__ float tf32r(float x) {
    uint32_t u;
    asm("cvt.rna.tf32.f32 %0, %1;" : "=r"(u) : "f"(x));
    return __uint_as_float(u);
}

__device__ __forceinline__ void mma8(float d[4], const uint32_t a[4], const uint32_t b[2]) {
    asm volatile(
        "mma.sync.aligned.m16n8k8.row.col.f32.tf32.tf32.f32 "
        "{%0,%1,%2,%3}, {%4,%5,%6,%7}, {%8,%9}, {%0,%1,%2,%3};\n"
        : "+f"(d[0]), "+f"(d[1]), "+f"(d[2]), "+f"(d[3])
        : "r"(a[0]), "r"(a[1]), "r"(a[2]), "r"(a[3]), "r"(b[0]), "r"(b[1]));
}

// ---------------------------------------------------------------
__global__ void zero_kernel() {
    int i = blockIdx.x * blockDim.x + threadIdx.x;
    if (i < Nn * Ff) d_sum[i] = 0.0f;
    if (i < Nn)      d_cnt[i] = 0.0f;
}

__global__ void prep_kernel(const float* __restrict__ W1, const float* __restrict__ b1,
                            const float* __restrict__ g1, const float* __restrict__ be1,
                            const float* __restrict__ rm1, const float* __restrict__ rv1,
                            const float* __restrict__ W2, const float* __restrict__ b2,
                            const float* __restrict__ g2, const float* __restrict__ be2,
                            const float* __restrict__ rm2, const float* __restrict__ rv2,
                            const float* __restrict__ W3) {
    int i = blockIdx.x * blockDim.x + threadIdx.x;
    if (i < 512 * 128) {
        int j = i >> 7, k = i & 127, o = j & 255;
        float s = g1[o] * rsqrtf(rv1[o] + EPS);
        float w = (j < 256) ? (W1[o * 256 + k] - W1[o * 256 + 128 + k])
                            : W1[o * 256 + 128 + k];
        d_C[i] = tf32r(s * w);
    }
    if (i < 256 * 256) {
        int o = i >> 8;
        float s = g2[o] * rsqrtf(rv2[o] + EPS);
        d_W2f[i] = tf32r(s * W2[i]);
    }
    if (i < 128 * 256) d_W3r[i] = tf32r(W3[i]);
    if (i < 256) {
        float s1v = g1[i] * rsqrtf(rv1[i] + EPS);
        d_b1f[i] = b1[i] * s1v + (be1[i] - rm1[i] * s1v);
        float s2v = g2[i] * rsqrtf(rv2[i] + EPS);
        d_b2f[i] = b2[i] * s2v + (be2[i] - rm2[i] * s2v);
    }
}

// UV = x @ C^T  via tf32 mma. Block tile: 64 nodes x 256 C-rows. grid (313, 2).
#define SXU 132   // 132 % 32 == 4
#define UVSMEM ((64 + 256) * SXU * 4)
__global__ __launch_bounds__(256, 1) void uv_gemm(const float* __restrict__ x) {
    extern __shared__ float sm[];
    float* xs = sm;                // [64][SXU]
    float* cs = sm + 64 * SXU;     // [256][SXU]
    int t = threadIdx.x, lane = t & 31, wid = t >> 5;
    int rowBase = blockIdx.x * 64;
    int cb = blockIdx.y * 256;

#pragma unroll
    for (int j = 0; j < 8; ++j) {
        int idx = t + j * 256;
        int r = idx >> 5, c4 = idx & 31;
        int gr = rowBase + r;
        float4 v = (gr < Nn) ? *(const float4*)(x + (size_t)gr * 128 + c4 * 4)
                             : make_float4(0.f, 0.f, 0.f, 0.f);
        float4 w = make_float4(tf32r(v.x), tf32r(v.y), tf32r(v.z), tf32r(v.w));
        *(float4*)(xs + r * SXU + c4 * 4) = w;
    }
#pragma unroll
    for (int j = 0; j < 32; ++j) {
        int idx = t + j * 256;
        int n = idx >> 5, c4 = idx & 31;
        float4 v = *(const float4*)(d_C + (size_t)(cb + n) * 128 + c4 * 4);
        *(float4*)(cs + n * SXU + c4 * 4) = v;
    }
    __syncthreads();

    int warpM = wid >> 2, warpN = wid & 3;
    int rB = warpM * 32, cB = warpN * 64;
    int qr = lane >> 2, qc = lane & 3;

    float acc[2][8][4] = {};
#pragma unroll
    for (int ks = 0; ks < 16; ++ks) {
        int kk = ks * 8;
        uint32_t a[2][4];
#pragma unroll
        for (int mi = 0; mi < 2; ++mi) {
            int r0 = rB + mi * 16 + qr;
            a[mi][0] = __float_as_uint(xs[r0 * SXU + kk + qc]);
            a[mi][1] = __float_as_uint(xs[(r0 + 8) * SXU + kk + qc]);
            a[mi][2] = __float_as_uint(xs[r0 * SXU + kk + qc + 4]);
            a[mi][3] = __float_as_uint(xs[(r0 + 8) * SXU + kk + qc + 4]);
        }
#pragma unroll
        for (int ni = 0; ni < 8; ++ni) {
            int n0 = cB + ni * 8 + qr;
            uint32_t b[2];
            b[0] = __float_as_uint(cs[n0 * SXU + kk + qc]);
            b[1] = __float_as_uint(cs[n0 * SXU + kk + qc + 4]);
            mma8(acc[0][ni], a[0], b);
            mma8(acc[1][ni], a[1], b);
        }
    }
#pragma unroll
    for (int mi = 0; mi < 2; ++mi)
#pragma unroll
        for (int ni = 0; ni < 8; ++ni) {
            int r0 = rowBase + rB + mi * 16 + qr;
            int c0 = cb + cB + ni * 8 + 2 * qc;
            if (r0 < Nn)
                *(float2*)(d_UV + (size_t)r0 * 512 + c0) =
                    make_float2(acc[mi][ni][0], acc[mi][ni][1]);
            if (r0 + 8 < Nn)
                *(float2*)(d_UV + (size_t)(r0 + 8) * 512 + c0) =
                    make_float2(acc[mi][ni][2], acc[mi][ni][3]);
        }
}

// edge_index is int32 on the wire (JAX x64 disabled). src=ei[i], dst=ei[E+i].
__global__ void degree_kernel(const int* __restrict__ ei) {
    int i = blockIdx.x * blockDim.x + threadIdx.x;
    if (i < Ee) atomicAdd(&d_cnt[ei[Ee + i]], 1.0f);
}

// Fused per-edge MLP on tensor cores. 128 edges/block, 16 warps.
#define EDGESMEM ((EPB * SA + 256 * SB) * 4)
__global__ __launch_bounds__(THREADS, 1) void edge_kernel(const int* __restrict__ ei,
                                                          const float* __restrict__ b3) {
    extern __shared__ float sm[];
    float* hin = sm;               // [128][SA]  (layer-1 out, then layer-2 out)
    float* wt  = sm + EPB * SA;    // [256][SB] weight k-slices
    __shared__ int s_src[EPB], s_dst[EPB];
    __shared__ float s_b2[256], s_b3[128];

    int t = threadIdx.x, lane = t & 31, wid = t >> 5;
    int e0 = blockIdx.x * EPB;

    if (t < EPB)                 s_src[t] = ei[e0 + t];
    else if (t < 2 * EPB)        s_dst[t - EPB] = ei[Ee + e0 + (t - EPB)];
    if (t < 256) s_b2[t] = d_b2f[t];
    else if (t < 384) s_b3[t - 256] = b3[t - 256];
    __syncthreads();

    // ---- phase 1: layer-1 gather + relu -> hin (tf32) ----
    {
        int col = t & 255;
        int ebase = (t >> 8) * 64;     // threads 0..255 do edges 0..63; 256..511 do 64..127
        float b1v = d_b1f[col];
#pragma unroll 4
        for (int e = ebase; e < ebase + 64; ++e) {
            float v = d_UV[(size_t)s_dst[e] * 512 + col]
                    + d_UV[(size_t)s_src[e] * 512 + 256 + col] + b1v;
            hin[e * SA + col] = tf32r(fmaxf(v, 0.0f));
        }
    }

    int warpM = wid >> 2, warpN = wid & 3;       // 4x4 warp grid
    int rB = warpM * 32;
    int qr = lane >> 2, qc = lane & 3;

    // ---- layer 2: [128,256] = hin[128,256] @ W2f^T, warp tile 32x64 ----
    float acc[2][8][4] = {};
    {
        int cB = warpN * 64;
        for (int kc = 0; kc < 4; ++kc) {
            __syncthreads();   // wt free / (kc==0) hin phase-1 writes done
#pragma unroll
            for (int j = 0; j < 8; ++j) {        // stage wt[256][64]
                int idx = t + j * THREADS;       // 0..4095
                int n = idx >> 4, k4 = idx & 15;
                float4 w = *(const float4*)(d_W2f + (size_t)n * 256 + kc * 64 + k4 * 4);
                *(float4*)(wt + n * SB + k4 * 4) = w;
            }
            __syncthreads();
#pragma unroll
            for (int ks = 0; ks < 8; ++ks) {
                int kk = ks * 8;
                int kg = kc * 64 + kk;
                uint32_t a[2][4];
#pragma unroll
                for (int mi = 0; mi < 2; ++mi) {
                    int r0 = rB + mi * 16 + qr;
                    a[mi][0] = __float_as_uint(hin[r0 * SA + kg + qc]);
                    a[mi][1] = __float_as_uint(hin[(r0 + 8) * SA + kg + qc]);
                    a[mi][2] = __float_as_uint(hin[r0 * SA + kg + qc + 4]);
                    a[mi][3] = __float_as_uint(hin[(r0 + 8) * SA + kg + qc + 4]);
                }
#pragma unroll
                for (int ni = 0; ni < 8; ++ni) {
                    int n0 = cB + ni * 8 + qr;
                    uint32_t b[2];
                    b[0] = __float_as_uint(wt[n0 * SB + kk + qc]);
                    b[1] = __float_as_uint(wt[n0 * SB + kk + qc + 4]);
                    mma8(acc[0][ni], a[0], b);
                    mma8(acc[1][ni], a[1], b);
                }
            }
        }
        __syncthreads();   // all layer-2 reads of hin done
        // bias + relu + tf32, write back over hin
#pragma unroll
        for (int mi = 0; mi < 2; ++mi)
#pragma unroll
            for (int ni = 0; ni < 8; ++ni) {
                int r0 = rB + mi * 16 + qr;
                int c0 = cB + ni * 8 + 2 * qc;
                hin[r0 * SA + c0]           = tf32r(fmaxf(acc[mi][ni][0] + s_b2[c0], 0.f));
                hin[r0 * SA + c0 + 1]       = tf32r(fmaxf(acc[mi][ni][1] + s_b2[c0 + 1], 0.f));
                hin[(r0 + 8) * SA + c0]     = tf32r(fmaxf(acc[mi][ni][2] + s_b2[c0], 0.f));
                hin[(r0 + 8) * SA + c0 + 1] = tf32r(fmaxf(acc[mi][ni][3] + s_b2[c0 + 1], 0.f));
            }
    }

    // ---- layer 3: [128,128] = h2[128,256] @ W3^T, warp tile 32x32 ----
    float acc3[2][4][4] = {};
    {
        int cB = warpN * 32;
        for (int kc = 0; kc < 4; ++kc) {
            __syncthreads();   // wt free; h2 writeback ordered before kc==0 stage
#pragma unroll
            for (int j = 0; j < 4; ++j) {        // stage wt[128][64]
                int idx = t + j * THREADS;       // 0..2047
                int n = idx >> 4, k4 = idx & 15;
                float4 w = *(const float4*)(d_W3r + (size_t)n * 256 + kc * 64 + k4 * 4);
                *(float4*)(wt + n * SB + k4 * 4) = w;
            }
            __syncthreads();
#pragma unroll
            for (int ks = 0; ks < 8; ++ks) {
                int kk = ks * 8;
                int kg = kc * 64 + kk;
                uint32_t a[2][4];
#pragma unroll
                for (int mi = 0; mi < 2; ++mi) {
                    int r0 = rB + mi * 16 + qr;
                    a[mi][0] = __float_as_uint(hin[r0 * SA + kg + qc]);
                    a[mi][1] = __float_as_uint(hin[(r0 + 8) * SA + kg + qc]);
                    a[mi][2] = __float_as_uint(hin[r0 * SA + kg + qc + 4]);
                    a[mi][3] = __float_as_uint(hin[(r0 + 8) * SA + kg + qc + 4]);
                }
#pragma unroll
                for (int ni = 0; ni < 4; ++ni) {
                    int n0 = cB + ni * 8 + qr;
                    uint32_t b[2];
                    b[0] = __float_as_uint(wt[n0 * SB + kk + qc]);
                    b[1] = __float_as_uint(wt[n0 * SB + kk + qc + 4]);
                    mma8(acc3[0][ni], a[0], b);
                    mma8(acc3[1][ni], a[1], b);
                }
            }
        }
        // scatter: bias + vector atomic into d_sum[dst]
#pragma unroll
        for (int mi = 0; mi < 2; ++mi)
#pragma unroll
            for (int ni = 0; ni < 4; ++ni) {
                int r0 = rB + mi * 16 + qr;
                int c0 = cB + ni * 8 + 2 * qc;
                float bx = s_b3[c0], by = s_b3[c0 + 1];
                float* p0 = d_sum + (size_t)s_dst[r0] * Ff + c0;
                float* p1 = d_sum + (size_t)s_dst[r0 + 8] * Ff + c0;
                asm volatile("red.global.add.v2.f32 [%0], {%1,%2};"
                             :: "l"(p0), "f"(acc3[mi][ni][0] + bx), "f"(acc3[mi][ni][1] + by)
                             : "memory");
                asm volatile("red.global.add.v2.f32 [%0], {%1,%2};"
                             :: "l"(p1), "f"(acc3[mi][ni][2] + bx), "f"(acc3[mi][ni][3] + by)
                             : "memory");
            }
    }
}

__global__ void final_kernel(float* __restrict__ out) {
    int i = blockIdx.x * blockDim.x + threadIdx.x;
    if (i < Nn * Ff) {
        int n = i >> 7;
        float c = fmaxf(d_cnt[n], 1.0f);
        out[i] = tanhf(d_sum[i] / c);
    }
}

// ---------------------------------------------------------------
extern "C" void kernel_launch(void* const* d_in, const int* in_sizes, int n_in,
                              void* d_out, int out_size) {
    const float* x  = (const float*)d_in[0];
    const int*   ei = (const int*)d_in[1];     // int32 (JAX x64 disabled)
    const float* W1 = (const float*)d_in[2];
    const float* b1 = (const float*)d_in[3];
    const float* g1 = (const float*)d_in[4];
    const float* be1 = (const float*)d_in[5];
    const float* rm1 = (const float*)d_in[6];
    const float* rv1 = (const float*)d_in[7];
    const float* W2 = (const float*)d_in[8];
    const float* b2 = (const float*)d_in[9];
    const float* g2 = (const float*)d_in[10];
    const float* be2 = (const float*)d_in[11];
    const float* rm2 = (const float*)d_in[12];
    const float* rv2 = (const float*)d_in[13];
    const float* W3 = (const float*)d_in[14];
    const float* b3 = (const float*)d_in[15];
    float* out = (float*)d_out;

    cudaFuncSetAttribute(uv_gemm, cudaFuncAttributeMaxDynamicSharedMemorySize, UVSMEM);
    cudaFuncSetAttribute(edge_kernel, cudaFuncAttributeMaxDynamicSharedMemorySize, EDGESMEM);

    zero_kernel<<<(Nn * Ff + 255) / 256, 256>>>();
    prep_kernel<<<(512 * 128 + 255) / 256, 256>>>(W1, b1, g1, be1, rm1, rv1,
                                                  W2, b2, g2, be2, rm2, rv2, W3);
    uv_gemm<<<dim3((Nn + 63) / 64, 2), 256, UVSMEM>>>(x);
    degree_kernel<<<(Ee + 255) / 256, 256>>>(ei);
    edge_kernel<<<Ee / EPB, THREADS, EDGESMEM>>>(ei, b3);
    final_kernel<<<(Nn * Ff + 255) / 256, 256>>>(out);
}

// round 6
// speedup vs baseline: 6.8793x; 1.7880x over previous
#include <cuda_runtime.h>
#include <cuda_fp16.h>
#include <math.h>
#include <stdint.h>

#define Nn 20000
#define Ee 320000
#define Ff 128
#define EPS 1e-5f

#define EPB 64           // edges per block
#define THREADS 256
#define SAH2 132         // hin stride in half2 words; 132 % 32 == 4 -> conflict-free
#define SBH2 36          // wt stride in half2 words; 36 % 32 == 4

// ---- device scratch ----
__device__ float  d_C[512 * 128];            // folded layer-1 weights (tf32-rounded)
__device__ __half d_W2h[256 * 256];          // folded layer-2 weights (fp16)
__device__ __half d_W3h[128 * 256];          // layer-3 weights (fp16)
__device__ float  d_b1f[256];
__device__ float  d_b2f[256];
__device__ __half d_UVh[(size_t)Nn * 512];   // u (cols 0..255), v (cols 256..511), fp16
__device__ float  d_sum[(size_t)Nn * Ff];
__device__ float  d_cnt[Nn];

__device__ __forceinline__ float tf32r(float x) {
    uint32_t u;
    asm("cvt.rna.tf32.f32 %0, %1;" : "=r"(u) : "f"(x));
    return __uint_as_float(u);
}

__device__ __forceinline__ void mma8(float d[4], const uint32_t a[4], const uint32_t b[2]) {
    asm volatile(
        "mma.sync.aligned.m16n8k8.row.col.f32.tf32.tf32.f32 "
        "{%0,%1,%2,%3}, {%4,%5,%6,%7}, {%8,%9}, {%0,%1,%2,%3};\n"
        : "+f"(d[0]), "+f"(d[1]), "+f"(d[2]), "+f"(d[3])
        : "r"(a[0]), "r"(a[1]), "r"(a[2]), "r"(a[3]), "r"(b[0]), "r"(b[1]));
}

__device__ __forceinline__ void mma16(float d[4], const uint32_t a[4], const uint32_t b[2]) {
    asm volatile(
        "mma.sync.aligned.m16n8k16.row.col.f32.f16.f16.f32 "
        "{%0,%1,%2,%3}, {%4,%5,%6,%7}, {%8,%9}, {%0,%1,%2,%3};\n"
        : "+f"(d[0]), "+f"(d[1]), "+f"(d[2]), "+f"(d[3])
        : "r"(a[0]), "r"(a[1]), "r"(a[2]), "r"(a[3]), "r"(b[0]), "r"(b[1]));
}

// ---------------------------------------------------------------
__global__ void zero_kernel() {
    int i = blockIdx.x * blockDim.x + threadIdx.x;
    if (i < Nn * Ff) d_sum[i] = 0.0f;
    if (i < Nn)      d_cnt[i] = 0.0f;
}

__global__ void prep_kernel(const float* __restrict__ W1, const float* __restrict__ b1,
                            const float* __restrict__ g1, const float* __restrict__ be1,
                            const float* __restrict__ rm1, const float* __restrict__ rv1,
                            const float* __restrict__ W2, const float* __restrict__ b2,
                            const float* __restrict__ g2, const float* __restrict__ be2,
                            const float* __restrict__ rm2, const float* __restrict__ rv2,
                            const float* __restrict__ W3) {
    int i = blockIdx.x * blockDim.x + threadIdx.x;
    if (i < 512 * 128) {
        int j = i >> 7, k = i & 127, o = j & 255;
        float s = g1[o] * rsqrtf(rv1[o] + EPS);
        float w = (j < 256) ? (W1[o * 256 + k] - W1[o * 256 + 128 + k])
                            : W1[o * 256 + 128 + k];
        d_C[i] = tf32r(s * w);
    }
    if (i < 256 * 256) {
        int o = i >> 8;
        float s = g2[o] * rsqrtf(rv2[o] + EPS);
        d_W2h[i] = __float2half(s * W2[i]);
    }
    if (i < 128 * 256) d_W3h[i] = __float2half(W3[i]);
    if (i < 256) {
        float s1v = g1[i] * rsqrtf(rv1[i] + EPS);
        d_b1f[i] = b1[i] * s1v + (be1[i] - rm1[i] * s1v);
        float s2v = g2[i] * rsqrtf(rv2[i] + EPS);
        d_b2f[i] = b2[i] * s2v + (be2[i] - rm2[i] * s2v);
    }
}

// UV = x @ C^T via tf32 mma (fp32 accum), output stored as fp16. grid (313, 2).
#define SXU 132   // 132 % 32 == 4
#define UVSMEM ((64 + 256) * SXU * 4)
__global__ __launch_bounds__(256, 1) void uv_gemm(const float* __restrict__ x) {
    extern __shared__ float sm[];
    float* xs = sm;                // [64][SXU]
    float* cs = sm + 64 * SXU;     // [256][SXU]
    int t = threadIdx.x, lane = t & 31, wid = t >> 5;
    int rowBase = blockIdx.x * 64;
    int cb = blockIdx.y * 256;

#pragma unroll
    for (int j = 0; j < 8; ++j) {
        int idx = t + j * 256;
        int r = idx >> 5, c4 = idx & 31;
        int gr = rowBase + r;
        float4 v = (gr < Nn) ? *(const float4*)(x + (size_t)gr * 128 + c4 * 4)
                             : make_float4(0.f, 0.f, 0.f, 0.f);
        float4 w = make_float4(tf32r(v.x), tf32r(v.y), tf32r(v.z), tf32r(v.w));
        *(float4*)(xs + r * SXU + c4 * 4) = w;
    }
#pragma unroll
    for (int j = 0; j < 32; ++j) {
        int idx = t + j * 256;
        int n = idx >> 5, c4 = idx & 31;
        float4 v = *(const float4*)(d_C + (size_t)(cb + n) * 128 + c4 * 4);
        *(float4*)(cs + n * SXU + c4 * 4) = v;
    }
    __syncthreads();

    int warpM = wid >> 2, warpN = wid & 3;
    int rB = warpM * 32, cB = warpN * 64;
    int qr = lane >> 2, qc = lane & 3;

    float acc[2][8][4] = {};
#pragma unroll
    for (int ks = 0; ks < 16; ++ks) {
        int kk = ks * 8;
        uint32_t a[2][4];
#pragma unroll
        for (int mi = 0; mi < 2; ++mi) {
            int r0 = rB + mi * 16 + qr;
            a[mi][0] = __float_as_uint(xs[r0 * SXU + kk + qc]);
            a[mi][1] = __float_as_uint(xs[(r0 + 8) * SXU + kk + qc]);
            a[mi][2] = __float_as_uint(xs[r0 * SXU + kk + qc + 4]);
            a[mi][3] = __float_as_uint(xs[(r0 + 8) * SXU + kk + qc + 4]);
        }
#pragma unroll
        for (int ni = 0; ni < 8; ++ni) {
            int n0 = cB + ni * 8 + qr;
            uint32_t b[2];
            b[0] = __float_as_uint(cs[n0 * SXU + kk + qc]);
            b[1] = __float_as_uint(cs[n0 * SXU + kk + qc + 4]);
            mma8(acc[0][ni], a[0], b);
            mma8(acc[1][ni], a[1], b);
        }
    }
#pragma unroll
    for (int mi = 0; mi < 2; ++mi)
#pragma unroll
        for (int ni = 0; ni < 8; ++ni) {
            int r0 = rowBase + rB + mi * 16 + qr;
            int c0 = cb + cB + ni * 8 + 2 * qc;
            if (r0 < Nn)
                *(__half2*)(d_UVh + (size_t)r0 * 512 + c0) =
                    __floats2half2_rn(acc[mi][ni][0], acc[mi][ni][1]);
            if (r0 + 8 < Nn)
                *(__half2*)(d_UVh + (size_t)(r0 + 8) * 512 + c0) =
                    __floats2half2_rn(acc[mi][ni][2], acc[mi][ni][3]);
        }
}

// edge_index is int32 on the wire (JAX x64 disabled). src=ei[i], dst=ei[E+i].
__global__ void degree_kernel(const int* __restrict__ ei) {
    int i = blockIdx.x * blockDim.x + threadIdx.x;
    if (i < Ee) atomicAdd(&d_cnt[ei[Ee + i]], 1.0f);
}

// Fused per-edge MLP, fp16 tensor cores. 64 edges/block, 8 warps, 2 CTAs/SM.
#define EDGESMEM ((EPB * SAH2 + 256 * SBH2) * 4)
__global__ __launch_bounds__(THREADS, 2) void edge_kernel(const int* __restrict__ ei,
                                                          const float* __restrict__ b3) {
    extern __shared__ __half2 sm2[];
    __half2* hin2 = sm2;                    // [64][SAH2]  (h1, then h2)
    __half2* wt2  = sm2 + EPB * SAH2;       // [256][SBH2]
    const __half* hinh = (const __half*)hin2;
    const __half* wth  = (const __half*)wt2;
    __shared__ int s_src[EPB], s_dst[EPB];
    __shared__ float s_b2[256], s_b3[128];

    int t = threadIdx.x, lane = t & 31, wid = t >> 5;
    int e0 = blockIdx.x * EPB;

    if (t < EPB)          s_src[t] = ei[e0 + t];
    else if (t < 2 * EPB) s_dst[t - EPB] = ei[Ee + e0 + (t - EPB)];
    s_b2[t] = d_b2f[t];
    if (t < 128) s_b3[t] = b3[t];
    __syncthreads();

    // ---- phase 1: layer-1 gather + relu -> hin (fp16) ----
    {
        int p = t & 127;               // half2 column 2p,2p+1
        int eb = (t >> 7) * 32;        // edges 0..31 or 32..63
        float b1x = d_b1f[2 * p], b1y = d_b1f[2 * p + 1];
#pragma unroll 4
        for (int e = eb; e < eb + 32; ++e) {
            __half2 hu = *(const __half2*)(d_UVh + (size_t)s_dst[e] * 512 + 2 * p);
            __half2 hv = *(const __half2*)(d_UVh + (size_t)s_src[e] * 512 + 256 + 2 * p);
            float2 fu = __half22float2(hu), fv = __half22float2(hv);
            hin2[e * SAH2 + p] = __floats2half2_rn(fmaxf(fu.x + fv.x + b1x, 0.f),
                                                   fmaxf(fu.y + fv.y + b1y, 0.f));
        }
    }

    int warpM = wid >> 2, warpN = wid & 3;   // 2x4 warp grid
    int rB = warpM * 32;
    int qr = lane >> 2, qc = lane & 3;

    // ---- layer 2: [64,256] = h1[64,256] @ W2h^T, warp tile 32x64, K chunks of 64 ----
    float acc[2][8][4] = {};
    {
        int cB = warpN * 64;
        for (int kc = 0; kc < 4; ++kc) {
            __syncthreads();
#pragma unroll
            for (int j = 0; j < 8; ++j) {            // stage wt[256][64 halfs]
                int idx = t + j * THREADS;           // 0..2047
                int n = idx >> 3, k8 = idx & 7;
                float4 w = *(const float4*)(d_W2h + (size_t)n * 256 + kc * 64 + k8 * 8);
                *(float4*)((__half*)wt2 + n * (2 * SBH2) + k8 * 8) = w;
            }
            __syncthreads();
#pragma unroll
            for (int ks = 0; ks < 4; ++ks) {
                int kh = ks * 16;                    // within chunk
                int kg = kc * 64 + kh;               // global k (halfs)
                uint32_t a[2][4];
#pragma unroll
                for (int mi = 0; mi < 2; ++mi) {
                    int r0 = rB + mi * 16 + qr;
                    a[mi][0] = *(const uint32_t*)(hinh + r0 * (2 * SAH2) + kg + 2 * qc);
                    a[mi][1] = *(const uint32_t*)(hinh + (r0 + 8) * (2 * SAH2) + kg + 2 * qc);
                    a[mi][2] = *(const uint32_t*)(hinh + r0 * (2 * SAH2) + kg + 8 + 2 * qc);
                    a[mi][3] = *(const uint32_t*)(hinh + (r0 + 8) * (2 * SAH2) + kg + 8 + 2 * qc);
                }
#pragma unroll
                for (int ni = 0; ni < 8; ++ni) {
                    int n0 = cB + ni * 8 + qr;
                    uint32_t b[2];
                    b[0] = *(const uint32_t*)(wth + n0 * (2 * SBH2) + kh + 2 * qc);
                    b[1] = *(const uint32_t*)(wth + n0 * (2 * SBH2) + kh + 8 + 2 * qc);
                    mma16(acc[0][ni], a[0], b);
                    mma16(acc[1][ni], a[1], b);
                }
            }
        }
        __syncthreads();   // all layer-2 reads of hin done
#pragma unroll
        for (int mi = 0; mi < 2; ++mi)
#pragma unroll
            for (int ni = 0; ni < 8; ++ni) {
                int r0 = rB + mi * 16 + qr;
                int c0 = cB + ni * 8 + 2 * qc;
                hin2[r0 * SAH2 + c0 / 2] =
                    __floats2half2_rn(fmaxf(acc[mi][ni][0] + s_b2[c0], 0.f),
                                      fmaxf(acc[mi][ni][1] + s_b2[c0 + 1], 0.f));
                hin2[(r0 + 8) * SAH2 + c0 / 2] =
                    __floats2half2_rn(fmaxf(acc[mi][ni][2] + s_b2[c0], 0.f),
                                      fmaxf(acc[mi][ni][3] + s_b2[c0 + 1], 0.f));
            }
    }

    // ---- layer 3: [64,128] = h2[64,256] @ W3h^T, warp tile 32x32 ----
    float acc3[2][4][4] = {};
    {
        int cB = warpN * 32;
        for (int kc = 0; kc < 4; ++kc) {
            __syncthreads();   // orders h2 writeback (kc==0) / wt reuse
#pragma unroll
            for (int j = 0; j < 4; ++j) {            // stage wt[128][64 halfs]
                int idx = t + j * THREADS;           // 0..1023
                int n = idx >> 3, k8 = idx & 7;
                float4 w = *(const float4*)(d_W3h + (size_t)n * 256 + kc * 64 + k8 * 8);
                *(float4*)((__half*)wt2 + n * (2 * SBH2) + k8 * 8) = w;
            }
            __syncthreads();
#pragma unroll
            for (int ks = 0; ks < 4; ++ks) {
                int kh = ks * 16;
                int kg = kc * 64 + kh;
                uint32_t a[2][4];
#pragma unroll
                for (int mi = 0; mi < 2; ++mi) {
                    int r0 = rB + mi * 16 + qr;
                    a[mi][0] = *(const uint32_t*)(hinh + r0 * (2 * SAH2) + kg + 2 * qc);
                    a[mi][1] = *(const uint32_t*)(hinh + (r0 + 8) * (2 * SAH2) + kg + 2 * qc);
                    a[mi][2] = *(const uint32_t*)(hinh + r0 * (2 * SAH2) + kg + 8 + 2 * qc);
                    a[mi][3] = *(const uint32_t*)(hinh + (r0 + 8) * (2 * SAH2) + kg + 8 + 2 * qc);
                }
#pragma unroll
                for (int ni = 0; ni < 4; ++ni) {
                    int n0 = cB + ni * 8 + qr;
                    uint32_t b[2];
                    b[0] = *(const uint32_t*)(wth + n0 * (2 * SBH2) + kh + 2 * qc);
                    b[1] = *(const uint32_t*)(wth + n0 * (2 * SBH2) + kh + 8 + 2 * qc);
                    mma16(acc3[0][ni], a[0], b);
                    mma16(acc3[1][ni], a[1], b);
                }
            }
        }
        // scatter: bias + vector atomics into d_sum[dst]
#pragma unroll
        for (int mi = 0; mi < 2; ++mi)
#pragma unroll
            for (int ni = 0; ni < 4; ++ni) {
                int r0 = rB + mi * 16 + qr;
                int c0 = cB + ni * 8 + 2 * qc;
                float bx = s_b3[c0], by = s_b3[c0 + 1];
                float* p0 = d_sum + (size_t)s_dst[r0] * Ff + c0;
                float* p1 = d_sum + (size_t)s_dst[r0 + 8] * Ff + c0;
                asm volatile("red.global.add.v2.f32 [%0], {%1,%2};"
                             :: "l"(p0), "f"(acc3[mi][ni][0] + bx), "f"(acc3[mi][ni][1] + by)
                             : "memory");
                asm volatile("red.global.add.v2.f32 [%0], {%1,%2};"
                             :: "l"(p1), "f"(acc3[mi][ni][2] + bx), "f"(acc3[mi][ni][3] + by)
                             : "memory");
            }
    }
}

__global__ void final_kernel(float* __restrict__ out) {
    int i = blockIdx.x * blockDim.x + threadIdx.x;
    if (i < Nn * Ff) {
        int n = i >> 7;
        float c = fmaxf(d_cnt[n], 1.0f);
        out[i] = tanhf(d_sum[i] / c);
    }
}

// ---------------------------------------------------------------
extern "C" void kernel_launch(void* const* d_in, const int* in_sizes, int n_in,
                              void* d_out, int out_size) {
    const float* x  = (const float*)d_in[0];
    const int*   ei = (const int*)d_in[1];     // int32 (JAX x64 disabled)
    const float* W1 = (const float*)d_in[2];
    const float* b1 = (const float*)d_in[3];
    const float* g1 = (const float*)d_in[4];
    const float* be1 = (const float*)d_in[5];
    const float* rm1 = (const float*)d_in[6];
    const float* rv1 = (const float*)d_in[7];
    const float* W2 = (const float*)d_in[8];
    const float* b2 = (const float*)d_in[9];
    const float* g2 = (const float*)d_in[10];
    const float* be2 = (const float*)d_in[11];
    const float* rm2 = (const float*)d_in[12];
    const float* rv2 = (const float*)d_in[13];
    const float* W3 = (const float*)d_in[14];
    const float* b3 = (const float*)d_in[15];
    float* out = (float*)d_out;

    cudaFuncSetAttribute(uv_gemm, cudaFuncAttributeMaxDynamicSharedMemorySize, UVSMEM);
    cudaFuncSetAttribute(edge_kernel, cudaFuncAttributeMaxDynamicSharedMemorySize, EDGESMEM);

    zero_kernel<<<(Nn * Ff + 255) / 256, 256>>>();
    prep_kernel<<<(512 * 128 + 255) / 256, 256>>>(W1, b1, g1, be1, rm1, rv1,
                                                  W2, b2, g2, be2, rm2, rv2, W3);
    uv_gemm<<<dim3((Nn + 63) / 64, 2), 256, UVSMEM>>>(x);
    degree_kernel<<<(Ee + 255) / 256, 256>>>(ei);
    edge_kernel<<<Ee / EPB, THREADS, EDGESMEM>>>(ei, b3);
    final_kernel<<<(Nn * Ff + 255) / 256, 256>>>(out);
}

// round 8
// speedup vs baseline: 9.1893x; 1.3358x over previous
#include <cuda_runtime.h>
#include <cuda_fp16.h>
#include <math.h>
#include <stdint.h>

#define Nn 20000
#define Ee 320000
#define Ff 128
#define EPS 1e-5f

#define EPB 64
#define THREADS 512
#define TILES (Ee / EPB)       // 5000
#define EDGE_GRID 148

// smem layout (bytes): W2 panels | W3 panels | h1 panels
#define OFF_W2 0               // 4 panels x 32768 (256 rows x 128B, SW128)
#define OFF_W3 131072          // 4 panels x 16384 (128 rows x 128B)
#define OFF_H1 196608          // 4 panels x 8192  (64 rows x 128B)
#define EDGESMEM 229376

#define SWZ(x) ((x) ^ (((x) >> 3) & 0x70))

// ---- device scratch ----
__device__ float   d_C[512 * 128];
__device__ __half  d_W2h[256 * 256];
__device__ __half  d_W3h[128 * 256];
__device__ float   d_b2f[256];
__device__ __half2 d_b1h2[128];
__device__ __half  d_UVh[(size_t)Nn * 512];
__device__ float   d_sum[(size_t)Nn * Ff];
__device__ float   d_cnt[Nn];

__device__ __forceinline__ float tf32r(float x) {
    uint32_t u;
    asm("cvt.rna.tf32.f32 %0, %1;" : "=r"(u) : "f"(x));
    return __uint_as_float(u);
}
__device__ __forceinline__ void mma8(float d[4], const uint32_t a[4], const uint32_t b[2]) {
    asm volatile(
        "mma.sync.aligned.m16n8k8.row.col.f32.tf32.tf32.f32 "
        "{%0,%1,%2,%3}, {%4,%5,%6,%7}, {%8,%9}, {%0,%1,%2,%3};\n"
        : "+f"(d[0]), "+f"(d[1]), "+f"(d[2]), "+f"(d[3])
        : "r"(a[0]), "r"(a[1]), "r"(a[2]), "r"(a[3]), "r"(b[0]), "r"(b[1]));
}
__device__ __forceinline__ void mma16(float d[4], const uint32_t a[4], const uint32_t b[2]) {
    asm volatile(
        "mma.sync.aligned.m16n8k16.row.col.f32.f16.f16.f32 "
        "{%0,%1,%2,%3}, {%4,%5,%6,%7}, {%8,%9}, {%0,%1,%2,%3};\n"
        : "+f"(d[0]), "+f"(d[1]), "+f"(d[2]), "+f"(d[3])
        : "r"(a[0]), "r"(a[1]), "r"(a[2]), "r"(a[3]), "r"(b[0]), "r"(b[1]));
}

// ---------------------------------------------------------------
__global__ void zero_kernel() {
    int i = blockIdx.x * blockDim.x + threadIdx.x;
    if (i < Nn * Ff) d_sum[i] = 0.0f;
    if (i < Nn)      d_cnt[i] = 0.0f;
}

__global__ void prep_kernel(const float* __restrict__ W1, const float* __restrict__ b1,
                            const float* __restrict__ g1, const float* __restrict__ be1,
                            const float* __restrict__ rm1, const float* __restrict__ rv1,
                            const float* __restrict__ W2, const float* __restrict__ b2,
                            const float* __restrict__ g2, const float* __restrict__ be2,
                            const float* __restrict__ rm2, const float* __restrict__ rv2,
                            const float* __restrict__ W3) {
    int i = blockIdx.x * blockDim.x + threadIdx.x;
    if (i < 512 * 128) {
        int j = i >> 7, k = i & 127, o = j & 255;
        float s = g1[o] * rsqrtf(rv1[o] + EPS);
        float w = (j < 256) ? (W1[o * 256 + k] - W1[o * 256 + 128 + k])
                            : W1[o * 256 + 128 + k];
        d_C[i] = tf32r(s * w);
    }
    if (i < 256 * 256) {
        int o = i >> 8;
        float s = g2[o] * rsqrtf(rv2[o] + EPS);
        d_W2h[i] = __float2half(s * W2[i]);
    }
    if (i < 128 * 256) d_W3h[i] = __float2half(W3[i]);
    if (i < 256) {
        float s2v = g2[i] * rsqrtf(rv2[i] + EPS);
        d_b2f[i] = b2[i] * s2v + (be2[i] - rm2[i] * s2v);
    }
    if (i < 128) {
        int o0 = 2 * i, o1 = 2 * i + 1;
        float sa = g1[o0] * rsqrtf(rv1[o0] + EPS);
        float sb = g1[o1] * rsqrtf(rv1[o1] + EPS);
        d_b1h2[i] = __floats2half2_rn(b1[o0] * sa + (be1[o0] - rm1[o0] * sa),
                                      b1[o1] * sb + (be1[o1] - rm1[o1] * sb));
    }
}

// UV = x @ C^T via tf32 mma (fp32 accum), output fp16. grid (313, 2).
#define SXU 132
#define UVSMEM ((64 + 256) * SXU * 4)
__global__ __launch_bounds__(256, 1) void uv_gemm(const float* __restrict__ x) {
    extern __shared__ float sm[];
    float* xs = sm;
    float* cs = sm + 64 * SXU;
    int t = threadIdx.x, lane = t & 31, wid = t >> 5;
    int rowBase = blockIdx.x * 64;
    int cb = blockIdx.y * 256;

#pragma unroll
    for (int j = 0; j < 8; ++j) {
        int idx = t + j * 256;
        int r = idx >> 5, c4 = idx & 31;
        int gr = rowBase + r;
        float4 v = (gr < Nn) ? *(const float4*)(x + (size_t)gr * 128 + c4 * 4)
                             : make_float4(0.f, 0.f, 0.f, 0.f);
        float4 w = make_float4(tf32r(v.x), tf32r(v.y), tf32r(v.z), tf32r(v.w));
        *(float4*)(xs + r * SXU + c4 * 4) = w;
    }
#pragma unroll
    for (int j = 0; j < 32; ++j) {
        int idx = t + j * 256;
        int n = idx >> 5, c4 = idx & 31;
        float4 v = *(const float4*)(d_C + (size_t)(cb + n) * 128 + c4 * 4);
        *(float4*)(cs + n * SXU + c4 * 4) = v;
    }
    __syncthreads();

    int warpM = wid >> 2, warpN = wid & 3;
    int rB = warpM * 32, cB = warpN * 64;
    int qr = lane >> 2, qc = lane & 3;

    float acc[2][8][4] = {};
#pragma unroll
    for (int ks = 0; ks < 16; ++ks) {
        int kk = ks * 8;
        uint32_t a[2][4];
#pragma unroll
        for (int mi = 0; mi < 2; ++mi) {
            int r0 = rB + mi * 16 + qr;
            a[mi][0] = __float_as_uint(xs[r0 * SXU + kk + qc]);
            a[mi][1] = __float_as_uint(xs[(r0 + 8) * SXU + kk + qc]);
            a[mi][2] = __float_as_uint(xs[r0 * SXU + kk + qc + 4]);
            a[mi][3] = __float_as_uint(xs[(r0 + 8) * SXU + kk + qc + 4]);
        }
#pragma unroll
        for (int ni = 0; ni < 8; ++ni) {
            int n0 = cB + ni * 8 + qr;
            uint32_t b[2];
            b[0] = __float_as_uint(cs[n0 * SXU + kk + qc]);
            b[1] = __float_as_uint(cs[n0 * SXU + kk + qc + 4]);
            mma8(acc[0][ni], a[0], b);
            mma8(acc[1][ni], a[1], b);
        }
    }
#pragma unroll
    for (int mi = 0; mi < 2; ++mi)
#pragma unroll
        for (int ni = 0; ni < 8; ++ni) {
            int r0 = rowBase + rB + mi * 16 + qr;
            int c0 = cb + cB + ni * 8 + 2 * qc;
            if (r0 < Nn)
                *(__half2*)(d_UVh + (size_t)r0 * 512 + c0) =
                    __floats2half2_rn(acc[mi][ni][0], acc[mi][ni][1]);
            if (r0 + 8 < Nn)
                *(__half2*)(d_UVh + (size_t)(r0 + 8) * 512 + c0) =
                    __floats2half2_rn(acc[mi][ni][2], acc[mi][ni][3]);
        }
}

// edge_index is int32 on the wire. src=ei[i], dst=ei[E+i].
__global__ void degree_kernel(const int* __restrict__ ei) {
    int i = blockIdx.x * blockDim.x + threadIdx.x;
    if (i < Ee) atomicAdd(&d_cnt[ei[Ee + i]], 1.0f);
}

// ---- persistent fused edge MLP, fp16 mma.sync, weights resident in smem ----
__global__ __launch_bounds__(THREADS, 1) void edge_kernel(const int* __restrict__ ei,
                                                          const float* __restrict__ b3) {
    extern __shared__ char smem[];
    int t = threadIdx.x, lane = t & 31, wid = t >> 5;

    // ---- load W2 into 4 swizzled panels (once per CTA) ----
#pragma unroll
    for (int j = 0; j < 16; ++j) {
        int item = j * THREADS + t;              // 8192 items
        int r = item >> 5, p = (item >> 3) & 3, ch = item & 7;
        uint4 w = *(const uint4*)(d_W2h + (size_t)r * 256 + p * 64 + ch * 8);
        *(uint4*)(smem + OFF_W2 + p * 32768 + SWZ(r * 128 + ch * 16)) = w;
    }
    // ---- load W3 into 4 swizzled panels ----
#pragma unroll
    for (int j = 0; j < 8; ++j) {
        int item = j * THREADS + t;              // 4096 items
        int r = item >> 5, p = (item >> 3) & 3, ch = item & 7;
        uint4 w = *(const uint4*)(d_W3h + (size_t)r * 256 + p * 64 + ch * 8);
        *(uint4*)(smem + OFF_W3 + p * 16384 + SWZ(r * 128 + ch * 16)) = w;
    }

    int warpM = wid >> 2, warpN = wid & 3;       // 4x4 warp grid
    int qr = lane >> 2, qc = lane & 3;
    uint32_t xv = (uint32_t)qr << 4;             // swizzle XOR: row&7 == qr for all rows used
    const __half2 z2 = __float2half2_rn(0.f);

    for (int tile = blockIdx.x; tile < TILES; tile += gridDim.x) {
        int e0 = tile * EPB;
        __syncthreads();   // h1 free: prev tile's layer-3 reads done

        // ---- gather + layer-1 -> h1 panels (fp16, swizzled) ----
#pragma unroll
        for (int j = 0; j < 4; ++j) {
            int item = j * THREADS + t;          // 2048 items
            int e = item >> 5, p = (item >> 3) & 3, ch = item & 7;
            int sidx = __ldg(ei + e0 + e);
            int didx = __ldg(ei + Ee + e0 + e);
            uint4 uu = *(const uint4*)(d_UVh + (size_t)didx * 512 + p * 64 + ch * 8);
            uint4 vv = *(const uint4*)(d_UVh + (size_t)sidx * 512 + 256 + p * 64 + ch * 8);
            const __half2* up = (const __half2*)&uu;
            const __half2* vp = (const __half2*)&vv;
            __half2 r[4];
#pragma unroll
            for (int q = 0; q < 4; ++q)
                r[q] = __hmax2(__hadd2(__hadd2(up[q], vp[q]), d_b1h2[p * 32 + ch * 4 + q]), z2);
            *(uint4*)(smem + OFF_H1 + p * 8192 + SWZ(e * 128 + ch * 16)) = *(uint4*)r;
        }
        __syncthreads();

        // ---- layer 2: [64,256] = h1 @ W2^T, warp tile 16x64, K=256 ----
        float acc[8][4] = {};
        {
            int rB = warpM * 16, cB = warpN * 64;
            int r0 = rB + qr, r1 = r0 + 8;
#pragma unroll
            for (int ks = 0; ks < 16; ++ks) {
                int kg = ks * 16, p = kg >> 6, kp = kg & 63;
                uint32_t c1 = ((kp + 2 * qc) * 2) ^ xv;
                uint32_t c2 = ((kp + 8 + 2 * qc) * 2) ^ xv;
                const char* hp = smem + OFF_H1 + p * 8192;
                uint32_t a[4];
                a[0] = *(const uint32_t*)(hp + r0 * 128 + c1);
                a[1] = *(const uint32_t*)(hp + r1 * 128 + c1);
                a[2] = *(const uint32_t*)(hp + r0 * 128 + c2);
                a[3] = *(const uint32_t*)(hp + r1 * 128 + c2);
                const char* wp = smem + OFF_W2 + p * 32768;
#pragma unroll
                for (int ni = 0; ni < 8; ++ni) {
                    int n0 = cB + ni * 8 + qr;
                    uint32_t b[2];
                    b[0] = *(const uint32_t*)(wp + n0 * 128 + c1);
                    b[1] = *(const uint32_t*)(wp + n0 * 128 + c2);
                    mma16(acc[ni], a, b);
                }
            }
        }
        __syncthreads();   // all layer-2 reads of h1 done

        // ---- bias + relu + fp16, write h2 over h1 panels ----
        {
            int rB = warpM * 16, cB = warpN * 64;
            int r0 = rB + qr, r1 = r0 + 8;
#pragma unroll
            for (int ni = 0; ni < 8; ++ni) {
                int c0 = cB + ni * 8 + 2 * qc;
                int p = c0 >> 6, cp = c0 & 63;
                float2 bb = __ldg((const float2*)(d_b2f + c0));
                char* hp = smem + OFF_H1 + p * 8192;
                uint32_t coff = ((uint32_t)(cp * 2)) ^ xv;
                *(__half2*)(hp + r0 * 128 + coff) =
                    __floats2half2_rn(fmaxf(acc[ni][0] + bb.x, 0.f),
                                      fmaxf(acc[ni][1] + bb.y, 0.f));
                *(__half2*)(hp + r1 * 128 + coff) =
                    __floats2half2_rn(fmaxf(acc[ni][2] + bb.x, 0.f),
                                      fmaxf(acc[ni][3] + bb.y, 0.f));
            }
        }
        __syncthreads();

        // ---- layer 3: [64,128] = h2 @ W3^T, warp tile 16x32, K=256 ----
        float acc3[4][4] = {};
        {
            int rB = warpM * 16, cB = warpN * 32;
            int r0 = rB + qr, r1 = r0 + 8;
#pragma unroll
            for (int ks = 0; ks < 16; ++ks) {
                int kg = ks * 16, p = kg >> 6, kp = kg & 63;
                uint32_t c1 = ((kp + 2 * qc) * 2) ^ xv;
                uint32_t c2 = ((kp + 8 + 2 * qc) * 2) ^ xv;
                const char* hp = smem + OFF_H1 + p * 8192;
                uint32_t a[4];
                a[0] = *(const uint32_t*)(hp + r0 * 128 + c1);
                a[1] = *(const uint32_t*)(hp + r1 * 128 + c1);
                a[2] = *(const uint32_t*)(hp + r0 * 128 + c2);
                a[3] = *(const uint32_t*)(hp + r1 * 128 + c2);
                const char* wp = smem + OFF_W3 + p * 16384;
#pragma unroll
                for (int ni = 0; ni < 4; ++ni) {
                    int n0 = cB + ni * 8 + qr;
                    uint32_t b[2];
                    b[0] = *(const uint32_t*)(wp + n0 * 128 + c1);
                    b[1] = *(const uint32_t*)(wp + n0 * 128 + c2);
                    mma16(acc3[ni], a, b);
                }
            }
        }

        // ---- scatter: bias + vector atomics into d_sum[dst] ----
        {
            int rB = warpM * 16, cB = warpN * 32;
            int d0 = __ldg(ei + Ee + e0 + rB + qr);
            int d1 = __ldg(ei + Ee + e0 + rB + qr + 8);
            float* p0b = d_sum + (size_t)d0 * Ff;
            float* p1b = d_sum + (size_t)d1 * Ff;
#pragma unroll
            for (int ni = 0; ni < 4; ++ni) {
                int c0 = cB + ni * 8 + 2 * qc;
                float2 bb = __ldg((const float2*)(b3 + c0));
                asm volatile("red.global.add.v2.f32 [%0], {%1,%2};"
                             :: "l"(p0b + c0), "f"(acc3[ni][0] + bb.x), "f"(acc3[ni][1] + bb.y)
                             : "memory");
                asm volatile("red.global.add.v2.f32 [%0], {%1,%2};"
                             :: "l"(p1b + c0), "f"(acc3[ni][2] + bb.x), "f"(acc3[ni][3] + bb.y)
                             : "memory");
            }
        }
    }
}

__global__ void final_kernel(float* __restrict__ out) {
    int i = blockIdx.x * blockDim.x + threadIdx.x;
    if (i < Nn * Ff) {
        int n = i >> 7;
        float c = fmaxf(d_cnt[n], 1.0f);
        out[i] = tanhf(d_sum[i] / c);
    }
}

// ---------------------------------------------------------------
extern "C" void kernel_launch(void* const* d_in, const int* in_sizes, int n_in,
                              void* d_out, int out_size) {
    const float* x  = (const float*)d_in[0];
    const int*   ei = (const int*)d_in[1];     // int32 (JAX x64 disabled)
    const float* W1 = (const float*)d_in[2];
    const float* b1 = (const float*)d_in[3];
    const float* g1 = (const float*)d_in[4];
    const float* be1 = (const float*)d_in[5];
    const float* rm1 = (const float*)d_in[6];
    const float* rv1 = (const float*)d_in[7];
    const float* W2 = (const float*)d_in[8];
    const float* b2 = (const float*)d_in[9];
    const float* g2 = (const float*)d_in[10];
    const float* be2 = (const float*)d_in[11];
    const float* rm2 = (const float*)d_in[12];
    const float* rv2 = (const float*)d_in[13];
    const float* W3 = (const float*)d_in[14];
    const float* b3 = (const float*)d_in[15];
    float* out = (float*)d_out;

    cudaFuncSetAttribute(uv_gemm, cudaFuncAttributeMaxDynamicSharedMemorySize, UVSMEM);
    cudaFuncSetAttribute(edge_kernel, cudaFuncAttributeMaxDynamicSharedMemorySize, EDGESMEM);

    zero_kernel<<<(Nn * Ff + 255) / 256, 256>>>();
    prep_kernel<<<(512 * 128 + 255) / 256, 256>>>(W1, b1, g1, be1, rm1, rv1,
                                                  W2, b2, g2, be2, rm2, rv2, W3);
    uv_gemm<<<dim3((Nn + 63) / 64, 2), 256, UVSMEM>>>(x);
    degree_kernel<<<(Ee + 255) / 256, 256>>>(ei);
    edge_kernel<<<EDGE_GRID, THREADS, EDGESMEM>>>(ei, b3);
    final_kernel<<<(Nn * Ff + 255) / 256, 256>>>(out);
}

// round 9
// speedup vs baseline: 9.8423x; 1.0711x over previous
#include <cuda_runtime.h>
#include <cuda_fp16.h>
#include <math.h>
#include <stdint.h>

#define Nn 20000
#define Ee 320000
#define Ff 128
#define EPS 1e-5f

#define EPB 128
#define THREADS 512
#define TILES (Ee / EPB)       // 2500
#define EDGE_GRID 148

// smem layout (bytes)
#define OFF_W2 0               // 4 panels x 32768 (256 rows x 128B, SW128) = 128K resident
#define OFF_H1 131072          // 4 panels x 16384 (128 rows x 128B) = 64K (h1, then h2)
#define OFF_W3 196608          // 2 chunk buffers x 16384 (128 rows x 128B)
#define EDGESMEM 229376

#define SWZ(x) ((x) ^ (((x) >> 3) & 0x70))

// ---- device scratch ----
__device__ float   d_C[512 * 128];
__device__ __half  d_W2h[256 * 256];
__device__ __half  d_W3h[128 * 256];
__device__ float   d_b2f[256];
__device__ __half2 d_b1h2[128];
__device__ __half  d_UVh[(size_t)Nn * 512];
__device__ float   d_sum[(size_t)Nn * Ff];
__device__ float   d_cnt[Nn];

__device__ __forceinline__ float tf32r(float x) {
    uint32_t u;
    asm("cvt.rna.tf32.f32 %0, %1;" : "=r"(u) : "f"(x));
    return __uint_as_float(u);
}
__device__ __forceinline__ void mma8(float d[4], const uint32_t a[4], const uint32_t b[2]) {
    asm volatile(
        "mma.sync.aligned.m16n8k8.row.col.f32.tf32.tf32.f32 "
        "{%0,%1,%2,%3}, {%4,%5,%6,%7}, {%8,%9}, {%0,%1,%2,%3};\n"
        : "+f"(d[0]), "+f"(d[1]), "+f"(d[2]), "+f"(d[3])
        : "r"(a[0]), "r"(a[1]), "r"(a[2]), "r"(a[3]), "r"(b[0]), "r"(b[1]));
}
__device__ __forceinline__ void mma16(float d[4], const uint32_t a[4], const uint32_t b[2]) {
    asm volatile(
        "mma.sync.aligned.m16n8k16.row.col.f32.f16.f16.f32 "
        "{%0,%1,%2,%3}, {%4,%5,%6,%7}, {%8,%9}, {%0,%1,%2,%3};\n"
        : "+f"(d[0]), "+f"(d[1]), "+f"(d[2]), "+f"(d[3])
        : "r"(a[0]), "r"(a[1]), "r"(a[2]), "r"(a[3]), "r"(b[0]), "r"(b[1]));
}

// ---------------------------------------------------------------
__global__ void zero_kernel() {
    int i = blockIdx.x * blockDim.x + threadIdx.x;
    if (i < Nn * Ff) d_sum[i] = 0.0f;
    if (i < Nn)      d_cnt[i] = 0.0f;
}

__global__ void prep_kernel(const float* __restrict__ W1, const float* __restrict__ b1,
                            const float* __restrict__ g1, const float* __restrict__ be1,
                            const float* __restrict__ rm1, const float* __restrict__ rv1,
                            const float* __restrict__ W2, const float* __restrict__ b2,
                            const float* __restrict__ g2, const float* __restrict__ be2,
                            const float* __restrict__ rm2, const float* __restrict__ rv2,
                            const float* __restrict__ W3) {
    int i = blockIdx.x * blockDim.x + threadIdx.x;
    if (i < 512 * 128) {
        int j = i >> 7, k = i & 127, o = j & 255;
        float s = g1[o] * rsqrtf(rv1[o] + EPS);
        float w = (j < 256) ? (W1[o * 256 + k] - W1[o * 256 + 128 + k])
                            : W1[o * 256 + 128 + k];
        d_C[i] = tf32r(s * w);
    }
    if (i < 256 * 256) {
        int o = i >> 8;
        float s = g2[o] * rsqrtf(rv2[o] + EPS);
        d_W2h[i] = __float2half(s * W2[i]);
    }
    if (i < 128 * 256) d_W3h[i] = __float2half(W3[i]);
    if (i < 256) {
        float s2v = g2[i] * rsqrtf(rv2[i] + EPS);
        d_b2f[i] = b2[i] * s2v + (be2[i] - rm2[i] * s2v);
    }
    if (i < 128) {
        int o0 = 2 * i, o1 = 2 * i + 1;
        float sa = g1[o0] * rsqrtf(rv1[o0] + EPS);
        float sb = g1[o1] * rsqrtf(rv1[o1] + EPS);
        d_b1h2[i] = __floats2half2_rn(b1[o0] * sa + (be1[o0] - rm1[o0] * sa),
                                      b1[o1] * sb + (be1[o1] - rm1[o1] * sb));
    }
}

// UV = x @ C^T via tf32 mma (fp32 accum), output fp16. grid (313, 2).
#define SXU 132
#define UVSMEM ((64 + 256) * SXU * 4)
__global__ __launch_bounds__(256, 1) void uv_gemm(const float* __restrict__ x) {
    extern __shared__ float sm[];
    float* xs = sm;
    float* cs = sm + 64 * SXU;
    int t = threadIdx.x, lane = t & 31, wid = t >> 5;
    int rowBase = blockIdx.x * 64;
    int cb = blockIdx.y * 256;

#pragma unroll
    for (int j = 0; j < 8; ++j) {
        int idx = t + j * 256;
        int r = idx >> 5, c4 = idx & 31;
        int gr = rowBase + r;
        float4 v = (gr < Nn) ? *(const float4*)(x + (size_t)gr * 128 + c4 * 4)
                             : make_float4(0.f, 0.f, 0.f, 0.f);
        float4 w = make_float4(tf32r(v.x), tf32r(v.y), tf32r(v.z), tf32r(v.w));
        *(float4*)(xs + r * SXU + c4 * 4) = w;
    }
#pragma unroll
    for (int j = 0; j < 32; ++j) {
        int idx = t + j * 256;
        int n = idx >> 5, c4 = idx & 31;
        float4 v = *(const float4*)(d_C + (size_t)(cb + n) * 128 + c4 * 4);
        *(float4*)(cs + n * SXU + c4 * 4) = v;
    }
    __syncthreads();

    int warpM = wid >> 2, warpN = wid & 3;
    int rB = warpM * 32, cB = warpN * 64;
    int qr = lane >> 2, qc = lane & 3;

    float acc[2][8][4] = {};
#pragma unroll
    for (int ks = 0; ks < 16; ++ks) {
        int kk = ks * 8;
        uint32_t a[2][4];
#pragma unroll
        for (int mi = 0; mi < 2; ++mi) {
            int r0 = rB + mi * 16 + qr;
            a[mi][0] = __float_as_uint(xs[r0 * SXU + kk + qc]);
            a[mi][1] = __float_as_uint(xs[(r0 + 8) * SXU + kk + qc]);
            a[mi][2] = __float_as_uint(xs[r0 * SXU + kk + qc + 4]);
            a[mi][3] = __float_as_uint(xs[(r0 + 8) * SXU + kk + qc + 4]);
        }
#pragma unroll
        for (int ni = 0; ni < 8; ++ni) {
            int n0 = cB + ni * 8 + qr;
            uint32_t b[2];
            b[0] = __float_as_uint(cs[n0 * SXU + kk + qc]);
            b[1] = __float_as_uint(cs[n0 * SXU + kk + qc + 4]);
            mma8(acc[0][ni], a[0], b);
            mma8(acc[1][ni], a[1], b);
        }
    }
#pragma unroll
    for (int mi = 0; mi < 2; ++mi)
#pragma unroll
        for (int ni = 0; ni < 8; ++ni) {
            int r0 = rowBase + rB + mi * 16 + qr;
            int c0 = cb + cB + ni * 8 + 2 * qc;
            if (r0 < Nn)
                *(__half2*)(d_UVh + (size_t)r0 * 512 + c0) =
                    __floats2half2_rn(acc[mi][ni][0], acc[mi][ni][1]);
            if (r0 + 8 < Nn)
                *(__half2*)(d_UVh + (size_t)(r0 + 8) * 512 + c0) =
                    __floats2half2_rn(acc[mi][ni][2], acc[mi][ni][3]);
        }
}

// edge_index is int32 on the wire. src=ei[i], dst=ei[E+i].
__global__ void degree_kernel(const int* __restrict__ ei) {
    int i = blockIdx.x * blockDim.x + threadIdx.x;
    if (i < Ee) atomicAdd(&d_cnt[ei[Ee + i]], 1.0f);
}

// ---- persistent fused edge MLP: 128 edges/tile, W2 resident, W3 K-streamed ----
__global__ __launch_bounds__(THREADS, 1) void edge_kernel(const int* __restrict__ ei,
                                                          const float* __restrict__ b3) {
    extern __shared__ char smem[];
    int t = threadIdx.x, lane = t & 31, wid = t >> 5;

    // ---- load W2 into 4 swizzled panels (once per CTA) ----
#pragma unroll
    for (int j = 0; j < 16; ++j) {
        int item = j * THREADS + t;              // 8192 items
        int r = item >> 5, p = (item >> 3) & 3, ch = item & 7;
        uint4 w = *(const uint4*)(d_W2h + (size_t)r * 256 + p * 64 + ch * 8);
        *(uint4*)(smem + OFF_W2 + p * 32768 + SWZ(r * 128 + ch * 16)) = w;
    }

    int warpM = wid >> 2, warpN = wid & 3;       // 4x4 warp grid
    int qr = lane >> 2, qc = lane & 3;
    uint32_t xv = (uint32_t)qr << 4;             // swizzle XOR (row&7 == qr on all rows used)
    const __half2 z2 = __float2half2_rn(0.f);

    // W3 chunk-stream item coords (per thread, 2 items of 16B per chunk)
    int w3n0 = t >> 3, w3ch = t & 7;             // item0: n = t>>3
    int w3n1 = (512 + t) >> 3;                   // item1
    uint32_t w3soff0 = SWZ(w3n0 * 128 + w3ch * 16);
    uint32_t w3soff1 = SWZ(w3n1 * 128 + w3ch * 16);

    for (int tile = blockIdx.x; tile < TILES; tile += gridDim.x) {
        int e0 = tile * EPB;
        __syncthreads();   // h1 free: prev tile's layer-3 reads done

        // ---- gather + layer-1 -> h1 panels (fp16, swizzled), 128 edges ----
#pragma unroll
        for (int j = 0; j < 8; ++j) {
            int item = j * THREADS + t;          // 4096 items
            int e = item >> 5, p = (item >> 3) & 3, ch = item & 7;
            int sidx = __ldg(ei + e0 + e);
            int didx = __ldg(ei + Ee + e0 + e);
            uint4 uu = *(const uint4*)(d_UVh + (size_t)didx * 512 + p * 64 + ch * 8);
            uint4 vv = *(const uint4*)(d_UVh + (size_t)sidx * 512 + 256 + p * 64 + ch * 8);
            const __half2* up = (const __half2*)&uu;
            const __half2* vp = (const __half2*)&vv;
            __half2 r[4];
#pragma unroll
            for (int q = 0; q < 4; ++q)
                r[q] = __hmax2(__hadd2(__hadd2(up[q], vp[q]), d_b1h2[p * 32 + ch * 4 + q]), z2);
            *(uint4*)(smem + OFF_H1 + p * 16384 + SWZ(e * 128 + ch * 16)) = *(uint4*)r;
        }
        __syncthreads();

        // ---- layer 2: [128,256] = h1 @ W2^T, warp tile 32x64, K=256 ----
        float acc[2][8][4] = {};
        {
            int rB = warpM * 32, cB = warpN * 64;
#pragma unroll
            for (int ks = 0; ks < 16; ++ks) {
                int kg = ks * 16, p = kg >> 6, kp = kg & 63;
                uint32_t c1 = ((kp + 2 * qc) * 2) ^ xv;
                uint32_t c2 = ((kp + 8 + 2 * qc) * 2) ^ xv;
                const char* hp = smem + OFF_H1 + p * 16384;
                uint32_t a[2][4];
#pragma unroll
                for (int mi = 0; mi < 2; ++mi) {
                    int r0 = rB + mi * 16 + qr;
                    a[mi][0] = *(const uint32_t*)(hp + r0 * 128 + c1);
                    a[mi][1] = *(const uint32_t*)(hp + (r0 + 8) * 128 + c1);
                    a[mi][2] = *(const uint32_t*)(hp + r0 * 128 + c2);
                    a[mi][3] = *(const uint32_t*)(hp + (r0 + 8) * 128 + c2);
                }
                const char* wp = smem + OFF_W2 + p * 32768;
#pragma unroll
                for (int ni = 0; ni < 8; ++ni) {
                    int n0 = cB + ni * 8 + qr;
                    uint32_t b[2];
                    b[0] = *(const uint32_t*)(wp + n0 * 128 + c1);
                    b[1] = *(const uint32_t*)(wp + n0 * 128 + c2);
                    mma16(acc[0][ni], a[0], b);
                    mma16(acc[1][ni], a[1], b);
                }
            }
        }

        // prefetch W3 chunks 0,1 (LDG into regs; STS after sync)
        uint4 wA0 = *(const uint4*)(d_W3h + (size_t)w3n0 * 256 + 0 * 64 + w3ch * 8);
        uint4 wA1 = *(const uint4*)(d_W3h + (size_t)w3n1 * 256 + 0 * 64 + w3ch * 8);
        uint4 wB0 = *(const uint4*)(d_W3h + (size_t)w3n0 * 256 + 1 * 64 + w3ch * 8);
        uint4 wB1 = *(const uint4*)(d_W3h + (size_t)w3n1 * 256 + 1 * 64 + w3ch * 8);

        __syncthreads();   // all layer-2 reads of h1 done

        // ---- bias + relu + fp16: h2 over h1 panels; stage W3 chunks 0,1 ----
        {
            int rB = warpM * 32, cB = warpN * 64;
#pragma unroll
            for (int mi = 0; mi < 2; ++mi) {
                int r0 = rB + mi * 16 + qr, r1 = r0 + 8;
#pragma unroll
                for (int ni = 0; ni < 8; ++ni) {
                    int c0 = cB + ni * 8 + 2 * qc;
                    int p = c0 >> 6, cp = c0 & 63;
                    float2 bb = __ldg((const float2*)(d_b2f + c0));
                    char* hp = smem + OFF_H1 + p * 16384;
                    uint32_t coff = ((uint32_t)(cp * 2)) ^ xv;
                    *(__half2*)(hp + r0 * 128 + coff) =
                        __floats2half2_rn(fmaxf(acc[mi][ni][0] + bb.x, 0.f),
                                          fmaxf(acc[mi][ni][1] + bb.y, 0.f));
                    *(__half2*)(hp + r1 * 128 + coff) =
                        __floats2half2_rn(fmaxf(acc[mi][ni][2] + bb.x, 0.f),
                                          fmaxf(acc[mi][ni][3] + bb.y, 0.f));
                }
            }
            *(uint4*)(smem + OFF_W3 + w3soff0) = wA0;
            *(uint4*)(smem + OFF_W3 + w3soff1) = wA1;
            *(uint4*)(smem + OFF_W3 + 16384 + w3soff0) = wB0;
            *(uint4*)(smem + OFF_W3 + 16384 + w3soff1) = wB1;
        }
        // prefetch W3 chunks 2,3
        wA0 = *(const uint4*)(d_W3h + (size_t)w3n0 * 256 + 2 * 64 + w3ch * 8);
        wA1 = *(const uint4*)(d_W3h + (size_t)w3n1 * 256 + 2 * 64 + w3ch * 8);
        wB0 = *(const uint4*)(d_W3h + (size_t)w3n0 * 256 + 3 * 64 + w3ch * 8);
        wB1 = *(const uint4*)(d_W3h + (size_t)w3n1 * 256 + 3 * 64 + w3ch * 8);

        __syncthreads();   // h2 + W3 chunks 0,1 visible

        // ---- layer 3: [128,128] = h2 @ W3^T, warp tile 32x32, K chunks ----
        float acc3[2][4][4] = {};
        int cB3 = warpN * 32, rB = warpM * 32;
#pragma unroll
        for (int kc = 0; kc < 2; ++kc) {
            const char* wp = smem + OFF_W3 + kc * 16384;
            const char* hp = smem + OFF_H1 + kc * 16384;      // A panel = kc
#pragma unroll
            for (int ks = 0; ks < 4; ++ks) {
                int kp = ks * 16;
                uint32_t c1 = ((kp + 2 * qc) * 2) ^ xv;
                uint32_t c2 = ((kp + 8 + 2 * qc) * 2) ^ xv;
                uint32_t a[2][4];
#pragma unroll
                for (int mi = 0; mi < 2; ++mi) {
                    int r0 = rB + mi * 16 + qr;
                    a[mi][0] = *(const uint32_t*)(hp + r0 * 128 + c1);
                    a[mi][1] = *(const uint32_t*)(hp + (r0 + 8) * 128 + c1);
                    a[mi][2] = *(const uint32_t*)(hp + r0 * 128 + c2);
                    a[mi][3] = *(const uint32_t*)(hp + (r0 + 8) * 128 + c2);
                }
#pragma unroll
                for (int ni = 0; ni < 4; ++ni) {
                    int n0 = cB3 + ni * 8 + qr;
                    uint32_t b[2];
                    b[0] = *(const uint32_t*)(wp + n0 * 128 + c1);
                    b[1] = *(const uint32_t*)(wp + n0 * 128 + c2);
                    mma16(acc3[0][ni], a[0], b);
                    mma16(acc3[1][ni], a[1], b);
                }
            }
        }
        __syncthreads();   // chunk buffers 0,1 consumed
        *(uint4*)(smem + OFF_W3 + w3soff0) = wA0;
        *(uint4*)(smem + OFF_W3 + w3soff1) = wA1;
        *(uint4*)(smem + OFF_W3 + 16384 + w3soff0) = wB0;
        *(uint4*)(smem + OFF_W3 + 16384 + w3soff1) = wB1;
        __syncthreads();   // chunks 2,3 staged
#pragma unroll
        for (int kc = 0; kc < 2; ++kc) {
            const char* wp = smem + OFF_W3 + kc * 16384;
            const char* hp = smem + OFF_H1 + (2 + kc) * 16384; // A panel = 2+kc
#pragma unroll
            for (int ks = 0; ks < 4; ++ks) {
                int kp = ks * 16;
                uint32_t c1 = ((kp + 2 * qc) * 2) ^ xv;
                uint32_t c2 = ((kp + 8 + 2 * qc) * 2) ^ xv;
                uint32_t a[2][4];
#pragma unroll
                for (int mi = 0; mi < 2; ++mi) {
                    int r0 = rB + mi * 16 + qr;
                    a[mi][0] = *(const uint32_t*)(hp + r0 * 128 + c1);
                    a[mi][1] = *(const uint32_t*)(hp + (r0 + 8) * 128 + c1);
                    a[mi][2] = *(const uint32_t*)(hp + r0 * 128 + c2);
                    a[mi][3] = *(const uint32_t*)(hp + (r0 + 8) * 128 + c2);
                }
#pragma unroll
                for (int ni = 0; ni < 4; ++ni) {
                    int n0 = cB3 + ni * 8 + qr;
                    uint32_t b[2];
                    b[0] = *(const uint32_t*)(wp + n0 * 128 + c1);
                    b[1] = *(const uint32_t*)(wp + n0 * 128 + c2);
                    mma16(acc3[0][ni], a[0], b);
                    mma16(acc3[1][ni], a[1], b);
                }
            }
        }

        // ---- scatter: bias + vector atomics into d_sum[dst] ----
#pragma unroll
        for (int mi = 0; mi < 2; ++mi) {
            int r0 = rB + mi * 16 + qr;
            int d0 = __ldg(ei + Ee + e0 + r0);
            int d1 = __ldg(ei + Ee + e0 + r0 + 8);
            float* p0b = d_sum + (size_t)d0 * Ff;
            float* p1b = d_sum + (size_t)d1 * Ff;
#pragma unroll
            for (int ni = 0; ni < 4; ++ni) {
                int c0 = cB3 + ni * 8 + 2 * qc;
                float2 bb = __ldg((const float2*)(b3 + c0));
                asm volatile("red.global.add.v2.f32 [%0], {%1,%2};"
                             :: "l"(p0b + c0), "f"(acc3[mi][ni][0] + bb.x),
                                "f"(acc3[mi][ni][1] + bb.y) : "memory");
                asm volatile("red.global.add.v2.f32 [%0], {%1,%2};"
                             :: "l"(p1b + c0), "f"(acc3[mi][ni][2] + bb.x),
                                "f"(acc3[mi][ni][3] + bb.y) : "memory");
            }
        }
    }
}

__global__ void final_kernel(float* __restrict__ out) {
    int i = blockIdx.x * blockDim.x + threadIdx.x;
    if (i < Nn * Ff) {
        int n = i >> 7;
        float c = fmaxf(d_cnt[n], 1.0f);
        out[i] = tanhf(d_sum[i] / c);
    }
}

// ---------------------------------------------------------------
extern "C" void kernel_launch(void* const* d_in, const int* in_sizes, int n_in,
                              void* d_out, int out_size) {
    const float* x  = (const float*)d_in[0];
    const int*   ei = (const int*)d_in[1];     // int32 (JAX x64 disabled)
    const float* W1 = (const float*)d_in[2];
    const float* b1 = (const float*)d_in[3];
    const float* g1 = (const float*)d_in[4];
    const float* be1 = (const float*)d_in[5];
    const float* rm1 = (const float*)d_in[6];
    const float* rv1 = (const float*)d_in[7];
    const float* W2 = (const float*)d_in[8];
    const float* b2 = (const float*)d_in[9];
    const float* g2 = (const float*)d_in[10];
    const float* be2 = (const float*)d_in[11];
    const float* rm2 = (const float*)d_in[12];
    const float* rv2 = (const float*)d_in[13];
    const float* W3 = (const float*)d_in[14];
    const float* b3 = (const float*)d_in[15];
    float* out = (float*)d_out;

    cudaFuncSetAttribute(uv_gemm, cudaFuncAttributeMaxDynamicSharedMemorySize, UVSMEM);
    cudaFuncSetAttribute(edge_kernel, cudaFuncAttributeMaxDynamicSharedMemorySize, EDGESMEM);

    zero_kernel<<<(Nn * Ff + 255) / 256, 256>>>();
    prep_kernel<<<(512 * 128 + 255) / 256, 256>>>(W1, b1, g1, be1, rm1, rv1,
                                                  W2, b2, g2, be2, rm2, rv2, W3);
    uv_gemm<<<dim3((Nn + 63) / 64, 2), 256, UVSMEM>>>(x);
    degree_kernel<<<(Ee + 255) / 256, 256>>>(ei);
    edge_kernel<<<EDGE_GRID, THREADS, EDGESMEM>>>(ei, b3);
    final_kernel<<<(Nn * Ff + 255) / 256, 256>>>(out);
}

// round 11
// speedup vs baseline: 10.4803x; 1.0648x over previous
#include <cuda_runtime.h>
#include <cuda_fp16.h>
#include <math.h>
#include <stdint.h>

#define Nn 20000
#define Ee 320000
#define Ff 128
#define EPS 1e-5f

#define EPB 128
#define THREADS 512
#define TILES (Ee / EPB)       // 2500
#define EDGE_GRID 148

// smem layout (bytes)
#define OFF_W2 0               // 4 panels x 32768 (256 rows x 128B, SW128) = 128K resident
#define OFF_H1 131072          // 4 panels x 16384 (128 rows x 128B) = 64K (h1, then h2)
#define OFF_W3 196608          // 2 chunk buffers x 16384 (128 rows x 128B)
#define EDGESMEM 229376

#define SWZ(x) ((x) ^ (((x) >> 3) & 0x70))

// ---- device scratch ----
__device__ float   d_C[512 * 128];
__device__ __half  d_W2h[256 * 256];
__device__ __half  d_W3h[128 * 256];
__device__ float   d_b2f[256];
__device__ __half2 d_b1h2[128];
__device__ __half  d_UVh[(size_t)Nn * 512];
__device__ float   d_sum[(size_t)Nn * Ff];
__device__ float   d_cnt[Nn];

__device__ __forceinline__ float tf32r(float x) {
    uint32_t u;
    asm("cvt.rna.tf32.f32 %0, %1;" : "=r"(u) : "f"(x));
    return __uint_as_float(u);
}
__device__ __forceinline__ void mma8(float d[4], const uint32_t a[4], const uint32_t b[2]) {
    asm volatile(
        "mma.sync.aligned.m16n8k8.row.col.f32.tf32.tf32.f32 "
        "{%0,%1,%2,%3}, {%4,%5,%6,%7}, {%8,%9}, {%0,%1,%2,%3};\n"
        : "+f"(d[0]), "+f"(d[1]), "+f"(d[2]), "+f"(d[3])
        : "r"(a[0]), "r"(a[1]), "r"(a[2]), "r"(a[3]), "r"(b[0]), "r"(b[1]));
}
__device__ __forceinline__ void mma16(float d[4], const uint32_t a[4], const uint32_t b[2]) {
    asm volatile(
        "mma.sync.aligned.m16n8k16.row.col.f32.f16.f16.f32 "
        "{%0,%1,%2,%3}, {%4,%5,%6,%7}, {%8,%9}, {%0,%1,%2,%3};\n"
        : "+f"(d[0]), "+f"(d[1]), "+f"(d[2]), "+f"(d[3])
        : "r"(a[0]), "r"(a[1]), "r"(a[2]), "r"(a[3]), "r"(b[0]), "r"(b[1]));
}
__device__ __forceinline__ void ldsm4(uint32_t r[4], uint32_t addr) {
    asm volatile("ldmatrix.sync.aligned.m8n8.x4.shared.b16 {%0,%1,%2,%3}, [%4];"
                 : "=r"(r[0]), "=r"(r[1]), "=r"(r[2]), "=r"(r[3]) : "r"(addr));
}
__device__ __forceinline__ uint32_t smem_u32(const void* p) {
    uint32_t a;
    asm("{ .reg .u64 t; cvta.to.shared.u64 t, %1; cvt.u32.u64 %0, t; }" : "=r"(a) : "l"(p));
    return a;
}

// ---------------------------------------------------------------
__global__ void zero_kernel() {
    int i = blockIdx.x * blockDim.x + threadIdx.x;
    if (i < Nn * Ff) d_sum[i] = 0.0f;
    if (i < Nn)      d_cnt[i] = 0.0f;
}

__global__ void prep_kernel(const float* __restrict__ W1, const float* __restrict__ b1,
                            const float* __restrict__ g1, const float* __restrict__ be1,
                            const float* __restrict__ rm1, const float* __restrict__ rv1,
                            const float* __restrict__ W2, const float* __restrict__ b2,
                            const float* __restrict__ g2, const float* __restrict__ be2,
                            const float* __restrict__ rm2, const float* __restrict__ rv2,
                            const float* __restrict__ W3) {
    int i = blockIdx.x * blockDim.x + threadIdx.x;
    if (i < 512 * 128) {
        int j = i >> 7, k = i & 127, o = j & 255;
        float s = g1[o] * rsqrtf(rv1[o] + EPS);
        float w = (j < 256) ? (W1[o * 256 + k] - W1[o * 256 + 128 + k])
                            : W1[o * 256 + 128 + k];
        d_C[i] = tf32r(s * w);
    }
    if (i < 256 * 256) {
        int o = i >> 8;
        float s = g2[o] * rsqrtf(rv2[o] + EPS);
        d_W2h[i] = __float2half(s * W2[i]);
    }
    if (i < 128 * 256) d_W3h[i] = __float2half(W3[i]);
    if (i < 256) {
        float s2v = g2[i] * rsqrtf(rv2[i] + EPS);
        d_b2f[i] = b2[i] * s2v + (be2[i] - rm2[i] * s2v);
    }
    if (i < 128) {
        int o0 = 2 * i, o1 = 2 * i + 1;
        float sa = g1[o0] * rsqrtf(rv1[o0] + EPS);
        float sb = g1[o1] * rsqrtf(rv1[o1] + EPS);
        d_b1h2[i] = __floats2half2_rn(b1[o0] * sa + (be1[o0] - rm1[o0] * sa),
                                      b1[o1] * sb + (be1[o1] - rm1[o1] * sb));
    }
}

// UV = x @ C^T via tf32 mma (fp32 accum), output fp16. grid (313, 2).
#define SXU 132
#define UVSMEM ((64 + 256) * SXU * 4)
__global__ __launch_bounds__(256, 1) void uv_gemm(const float* __restrict__ x) {
    extern __shared__ float sm[];
    float* xs = sm;
    float* cs = sm + 64 * SXU;
    int t = threadIdx.x, lane = t & 31, wid = t >> 5;
    int rowBase = blockIdx.x * 64;
    int cb = blockIdx.y * 256;

#pragma unroll
    for (int j = 0; j < 8; ++j) {
        int idx = t + j * 256;
        int r = idx >> 5, c4 = idx & 31;
        int gr = rowBase + r;
        float4 v = (gr < Nn) ? *(const float4*)(x + (size_t)gr * 128 + c4 * 4)
                             : make_float4(0.f, 0.f, 0.f, 0.f);
        float4 w = make_float4(tf32r(v.x), tf32r(v.y), tf32r(v.z), tf32r(v.w));
        *(float4*)(xs + r * SXU + c4 * 4) = w;
    }
#pragma unroll
    for (int j = 0; j < 32; ++j) {
        int idx = t + j * 256;
        int n = idx >> 5, c4 = idx & 31;
        float4 v = *(const float4*)(d_C + (size_t)(cb + n) * 128 + c4 * 4);
        *(float4*)(cs + n * SXU + c4 * 4) = v;
    }
    __syncthreads();

    int warpM = wid >> 2, warpN = wid & 3;
    int rB = warpM * 32, cB = warpN * 64;
    int qr = lane >> 2, qc = lane & 3;

    float acc[2][8][4] = {};
#pragma unroll
    for (int ks = 0; ks < 16; ++ks) {
        int kk = ks * 8;
        uint32_t a[2][4];
#pragma unroll
        for (int mi = 0; mi < 2; ++mi) {
            int r0 = rB + mi * 16 + qr;
            a[mi][0] = __float_as_uint(xs[r0 * SXU + kk + qc]);
            a[mi][1] = __float_as_uint(xs[(r0 + 8) * SXU + kk + qc]);
            a[mi][2] = __float_as_uint(xs[r0 * SXU + kk + qc + 4]);
            a[mi][3] = __float_as_uint(xs[(r0 + 8) * SXU + kk + qc + 4]);
        }
#pragma unroll
        for (int ni = 0; ni < 8; ++ni) {
            int n0 = cB + ni * 8 + qr;
            uint32_t b[2];
            b[0] = __float_as_uint(cs[n0 * SXU + kk + qc]);
            b[1] = __float_as_uint(cs[n0 * SXU + kk + qc + 4]);
            mma8(acc[0][ni], a[0], b);
            mma8(acc[1][ni], a[1], b);
        }
    }
#pragma unroll
    for (int mi = 0; mi < 2; ++mi)
#pragma unroll
        for (int ni = 0; ni < 8; ++ni) {
            int r0 = rowBase + rB + mi * 16 + qr;
            int c0 = cb + cB + ni * 8 + 2 * qc;
            if (r0 < Nn)
                *(__half2*)(d_UVh + (size_t)r0 * 512 + c0) =
                    __floats2half2_rn(acc[mi][ni][0], acc[mi][ni][1]);
            if (r0 + 8 < Nn)
                *(__half2*)(d_UVh + (size_t)(r0 + 8) * 512 + c0) =
                    __floats2half2_rn(acc[mi][ni][2], acc[mi][ni][3]);
        }
}

// edge_index is int32 on the wire. src=ei[i], dst=ei[E+i].
__global__ void degree_kernel(const int* __restrict__ ei) {
    int i = blockIdx.x * blockDim.x + threadIdx.x;
    if (i < Ee) atomicAdd(&d_cnt[ei[Ee + i]], 1.0f);
}

// ---- persistent fused edge MLP: ldmatrix fragments, W2 resident, W3 streamed ----
__global__ __launch_bounds__(THREADS, 1) void edge_kernel(const int* __restrict__ ei,
                                                          const float* __restrict__ b3) {
    extern __shared__ char smem[];
    uint32_t sb = smem_u32(smem);
    int t = threadIdx.x, lane = t & 31, wid = t >> 5;

    // ---- load W2 into 4 swizzled panels (once per CTA) ----
#pragma unroll
    for (int j = 0; j < 16; ++j) {
        int item = j * THREADS + t;              // 8192 items
        int r = item >> 5, p = (item >> 3) & 3, ch = item & 7;
        uint4 w = *(const uint4*)(d_W2h + (size_t)r * 256 + p * 64 + ch * 8);
        *(uint4*)(smem + OFF_W2 + p * 32768 + SWZ(r * 128 + ch * 16)) = w;
    }

    int warpM = wid >> 2, warpN = wid & 3;       // 4x4 warp grid
    int qr = lane >> 2, qc = lane & 3;
    uint32_t xorl = (uint32_t)(lane & 7) << 4;   // SW128 XOR for ldmatrix rows (row%8 == lane&7)
    uint32_t xorq = (uint32_t)qr << 4;           // SW128 XOR for epilogue rows (row%8 == qr)
    const __half2 z2 = __float2half2_rn(0.f);

    // ldmatrix per-lane bases
    uint32_t aColHi = ((lane >> 4) & 1) * 16;                 // +8 halfs for lanes 16-31
    uint32_t aBase  = sb + OFF_H1 + (warpM * 32 + (lane & 15)) * 128;
    uint32_t bRowOff = (uint32_t)((lane & 7) + ((lane >> 4) << 3));   // 0..15
    uint32_t bColHi  = ((lane >> 3) & 1) * 16;                // +8 halfs for lanes 8-15,24-31
    uint32_t b2Base  = sb + OFF_W2 + (warpN * 64 + bRowOff) * 128;
    uint32_t b3Base  = sb + OFF_W3 + (warpN * 32 + bRowOff) * 128;

    // W3 chunk-stream item coords (per thread, 2 items of 16B per chunk)
    int w3n0 = t >> 3, w3ch = t & 7;
    int w3n1 = (512 + t) >> 3;
    uint32_t w3soff0 = SWZ(w3n0 * 128 + w3ch * 16);
    uint32_t w3soff1 = SWZ(w3n1 * 128 + w3ch * 16);

    for (int tile = blockIdx.x; tile < TILES; tile += gridDim.x) {
        int e0 = tile * EPB;
        __syncthreads();   // h1 free: prev tile's layer-3 reads done

        // ---- gather + layer-1 -> h1 panels (fp16, swizzled), 128 edges ----
#pragma unroll
        for (int j = 0; j < 8; ++j) {
            int item = j * THREADS + t;          // 4096 items
            int e = item >> 5, p = (item >> 3) & 3, ch = item & 7;
            int sidx = __ldg(ei + e0 + e);
            int didx = __ldg(ei + Ee + e0 + e);
            uint4 uu = *(const uint4*)(d_UVh + (size_t)didx * 512 + p * 64 + ch * 8);
            uint4 vv = *(const uint4*)(d_UVh + (size_t)sidx * 512 + 256 + p * 64 + ch * 8);
            const __half2* up = (const __half2*)&uu;
            const __half2* vp = (const __half2*)&vv;
            __half2 r[4];
#pragma unroll
            for (int q = 0; q < 4; ++q)
                r[q] = __hmax2(__hadd2(__hadd2(up[q], vp[q]), d_b1h2[p * 32 + ch * 4 + q]), z2);
            *(uint4*)(smem + OFF_H1 + p * 16384 + SWZ(e * 128 + ch * 16)) = *(uint4*)r;
        }
        __syncthreads();

        // ---- layer 2: [128,256] = h1 @ W2^T, warp tile 32x64, ldmatrix frags ----
        float acc[2][8][4] = {};
        {
#pragma unroll
            for (int ks = 0; ks < 16; ++ks) {
                int kg = ks * 16, p = kg >> 6;
                uint32_t kp2 = (uint32_t)((kg & 63) * 2);
                uint32_t a0[4], a1[4];
                uint32_t acb = (kp2 + aColHi) ^ xorl;
                ldsm4(a0, aBase + p * 16384 + acb);
                ldsm4(a1, aBase + 2048 + p * 16384 + acb);
                uint32_t wb = b2Base + p * 32768 + ((kp2 + bColHi) ^ xorl);
#pragma unroll
                for (int ni2 = 0; ni2 < 4; ++ni2) {
                    uint32_t bb[4];
                    ldsm4(bb, wb + ni2 * 2048);
                    mma16(acc[0][2 * ni2],     a0, bb);
                    mma16(acc[1][2 * ni2],     a1, bb);
                    mma16(acc[0][2 * ni2 + 1], a0, bb + 2);
                    mma16(acc[1][2 * ni2 + 1], a1, bb + 2);
                }
            }
        }

        // prefetch W3 chunks 0,1 (LDG into regs; STS after sync)
        uint4 wA0 = *(const uint4*)(d_W3h + (size_t)w3n0 * 256 + 0 * 64 + w3ch * 8);
        uint4 wA1 = *(const uint4*)(d_W3h + (size_t)w3n1 * 256 + 0 * 64 + w3ch * 8);
        uint4 wB0 = *(const uint4*)(d_W3h + (size_t)w3n0 * 256 + 1 * 64 + w3ch * 8);
        uint4 wB1 = *(const uint4*)(d_W3h + (size_t)w3n1 * 256 + 1 * 64 + w3ch * 8);

        __syncthreads();   // all layer-2 reads of h1 done

        // ---- bias + relu + fp16: h2 over h1 panels; stage W3 chunks 0,1 ----
        {
            int rB = warpM * 32, cB = warpN * 64;
#pragma unroll
            for (int mi = 0; mi < 2; ++mi) {
                int r0 = rB + mi * 16 + qr, r1 = r0 + 8;
#pragma unroll
                for (int ni = 0; ni < 8; ++ni) {
                    int c0 = cB + ni * 8 + 2 * qc;
                    int p = c0 >> 6, cp = c0 & 63;
                    float2 bb = __ldg((const float2*)(d_b2f + c0));
                    char* hp = smem + OFF_H1 + p * 16384;
                    uint32_t coff = ((uint32_t)(cp * 2)) ^ xorq;   // row%8 == qr here
                    *(__half2*)(hp + r0 * 128 + coff) =
                        __floats2half2_rn(fmaxf(acc[mi][ni][0] + bb.x, 0.f),
                                          fmaxf(acc[mi][ni][1] + bb.y, 0.f));
                    *(__half2*)(hp + r1 * 128 + coff) =
                        __floats2half2_rn(fmaxf(acc[mi][ni][2] + bb.x, 0.f),
                                          fmaxf(acc[mi][ni][3] + bb.y, 0.f));
                }
            }
            *(uint4*)(smem + OFF_W3 + w3soff0) = wA0;
            *(uint4*)(smem + OFF_W3 + w3soff1) = wA1;
            *(uint4*)(smem + OFF_W3 + 16384 + w3soff0) = wB0;
            *(uint4*)(smem + OFF_W3 + 16384 + w3soff1) = wB1;
        }
        // prefetch W3 chunks 2,3
        wA0 = *(const uint4*)(d_W3h + (size_t)w3n0 * 256 + 2 * 64 + w3ch * 8);
        wA1 = *(const uint4*)(d_W3h + (size_t)w3n1 * 256 + 2 * 64 + w3ch * 8);
        wB0 = *(const uint4*)(d_W3h + (size_t)w3n0 * 256 + 3 * 64 + w3ch * 8);
        wB1 = *(const uint4*)(d_W3h + (size_t)w3n1 * 256 + 3 * 64 + w3ch * 8);

        __syncthreads();   // h2 + W3 chunks 0,1 visible

        // ---- layer 3: [128,128] = h2 @ W3^T, warp tile 32x32, ldmatrix frags ----
        float acc3[2][4][4] = {};
#pragma unroll
        for (int kc = 0; kc < 2; ++kc) {
            uint32_t wb3 = b3Base + kc * 16384;
            uint32_t ab3 = aBase + kc * 16384;          // A panel = kc
#pragma unroll
            for (int ks = 0; ks < 4; ++ks) {
                uint32_t kp2 = (uint32_t)(ks * 32);
                uint32_t a0[4], a1[4];
                uint32_t acb = (kp2 + aColHi) ^ xorl;
                ldsm4(a0, ab3 + acb);
                ldsm4(a1, ab3 + 2048 + acb);
                uint32_t wb = wb3 + ((kp2 + bColHi) ^ xorl);
#pragma unroll
                for (int ni2 = 0; ni2 < 2; ++ni2) {
                    uint32_t bb[4];
                    ldsm4(bb, wb + ni2 * 2048);
                    mma16(acc3[0][2 * ni2],     a0, bb);
                    mma16(acc3[1][2 * ni2],     a1, bb);
                    mma16(acc3[0][2 * ni2 + 1], a0, bb + 2);
                    mma16(acc3[1][2 * ni2 + 1], a1, bb + 2);
                }
            }
        }
        __syncthreads();   // chunk buffers 0,1 consumed
        *(uint4*)(smem + OFF_W3 + w3soff0) = wA0;
        *(uint4*)(smem + OFF_W3 + w3soff1) = wA1;
        *(uint4*)(smem + OFF_W3 + 16384 + w3soff0) = wB0;
        *(uint4*)(smem + OFF_W3 + 16384 + w3soff1) = wB1;
        __syncthreads();   // chunks 2,3 staged
#pragma unroll
        for (int kc = 0; kc < 2; ++kc) {
            uint32_t wb3 = b3Base + kc * 16384;
            uint32_t ab3 = aBase + (2 + kc) * 16384;    // A panel = 2+kc
#pragma unroll
            for (int ks = 0; ks < 4; ++ks) {
                uint32_t kp2 = (uint32_t)(ks * 32);
                uint32_t a0[4], a1[4];
                uint32_t acb = (kp2 + aColHi) ^ xorl;
                ldsm4(a0, ab3 + acb);
                ldsm4(a1, ab3 + 2048 + acb);
                uint32_t wb = wb3 + ((kp2 + bColHi) ^ xorl);
#pragma unroll
                for (int ni2 = 0; ni2 < 2; ++ni2) {
                    uint32_t bb[4];
                    ldsm4(bb, wb + ni2 * 2048);
                    mma16(acc3[0][2 * ni2],     a0, bb);
                    mma16(acc3[1][2 * ni2],     a1, bb);
                    mma16(acc3[0][2 * ni2 + 1], a0, bb + 2);
                    mma16(acc3[1][2 * ni2 + 1], a1, bb + 2);
                }
            }
        }

        // ---- scatter: bias + vector atomics into d_sum[dst] ----
        int rB = warpM * 32, cB3 = warpN * 32;
#pragma unroll
        for (int mi = 0; mi < 2; ++mi) {
            int r0 = rB + mi * 16 + qr;
            int d0 = __ldg(ei + Ee + e0 + r0);
            int d1 = __ldg(ei + Ee + e0 + r0 + 8);
            float* p0b = d_sum + (size_t)d0 * Ff;
            float* p1b = d_sum + (size_t)d1 * Ff;
#pragma unroll
            for (int ni = 0; ni < 4; ++ni) {
                int c0 = cB3 + ni * 8 + 2 * qc;
                float2 bb = __ldg((const float2*)(b3 + c0));
                asm volatile("red.global.add.v2.f32 [%0], {%1,%2};"
                             :: "l"(p0b + c0), "f"(acc3[mi][ni][0] + bb.x),
                                "f"(acc3[mi][ni][1] + bb.y) : "memory");
                asm volatile("red.global.add.v2.f32 [%0], {%1,%2};"
                             :: "l"(p1b + c0), "f"(acc3[mi][ni][2] + bb.x),
                                "f"(acc3[mi][ni][3] + bb.y) : "memory");
            }
        }
    }
}

__global__ void final_kernel(float* __restrict__ out) {
    int i = blockIdx.x * blockDim.x + threadIdx.x;
    if (i < Nn * Ff) {
        int n = i >> 7;
        float c = fmaxf(d_cnt[n], 1.0f);
        out[i] = tanhf(d_sum[i] / c);
    }
}

// ---------------------------------------------------------------
extern "C" void kernel_launch(void* const* d_in, const int* in_sizes, int n_in,
                              void* d_out, int out_size) {
    const float* x  = (const float*)d_in[0];
    const int*   ei = (const int*)d_in[1];     // int32 (JAX x64 disabled)
    const float* W1 = (const float*)d_in[2];
    const float* b1 = (const float*)d_in[3];
    const float* g1 = (const float*)d_in[4];
    const float* be1 = (const float*)d_in[5];
    const float* rm1 = (const float*)d_in[6];
    const float* rv1 = (const float*)d_in[7];
    const float* W2 = (const float*)d_in[8];
    const float* b2 = (const float*)d_in[9];
    const float* g2 = (const float*)d_in[10];
    const float* be2 = (const float*)d_in[11];
    const float* rm2 = (const float*)d_in[12];
    const float* rv2 = (const float*)d_in[13];
    const float* W3 = (const float*)d_in[14];
    const float* b3 = (const float*)d_in[15];
    float* out = (float*)d_out;

    cudaFuncSetAttribute(uv_gemm, cudaFuncAttributeMaxDynamicSharedMemorySize, UVSMEM);
    cudaFuncSetAttribute(edge_kernel, cudaFuncAttributeMaxDynamicSharedMemorySize, EDGESMEM);

    zero_kernel<<<(Nn * Ff + 255) / 256, 256>>>();
    prep_kernel<<<(512 * 128 + 255) / 256, 256>>>(W1, b1, g1, be1, rm1, rv1,
                                                  W2, b2, g2, be2, rm2, rv2, W3);
    uv_gemm<<<dim3((Nn + 63) / 64, 2), 256, UVSMEM>>>(x);
    degree_kernel<<<(Ee + 255) / 256, 256>>>(ei);
    edge_kernel<<<EDGE_GRID, THREADS, EDGESMEM>>>(ei, b3);
    final_kernel<<<(Nn * Ff + 255) / 256, 256>>>(out);
}

// round 13
// speedup vs baseline: 11.4591x; 1.0934x over previous
#include <cuda_runtime.h>
#include <cuda_fp16.h>
#include <math.h>
#include <stdint.h>

#define Nn 20000
#define Ee 320000
#define Ff 128
#define EPS 1e-5f

#define EPB 128
#define THREADS 512
#define TILES (Ee / EPB)       // 2500
#define EDGE_GRID 148

// edge kernel smem layout (bytes)
#define OFF_W2 0               // 4 panels x 32768 (256 rows x 128B, SW128) = 128K resident
#define OFF_H1 131072          // 4 panels x 16384 (128 rows x 128B) = 64K (h1, then h2)
#define OFF_W3 196608          // 2 chunk buffers x 16384 (128 rows x 128B)
#define EDGESMEM 229376

#define SWZ(x) ((x) ^ (((x) >> 3) & 0x70))

// ---- device scratch ----
__device__ __half  d_Ch[512 * 128];          // folded layer-1 weights (fp16)
__device__ __half  d_W2h[256 * 256];
__device__ __half  d_W3h[128 * 256];
__device__ float   d_b2f[256];
__device__ __half2 d_b1h2[128];
__device__ __half  d_UVh[(size_t)Nn * 512];
__device__ float   d_sum[(size_t)Nn * Ff];
__device__ float   d_cnt[Nn];

__device__ __forceinline__ void mma16(float d[4], const uint32_t a[4], const uint32_t b[2]) {
    asm volatile(
        "mma.sync.aligned.m16n8k16.row.col.f32.f16.f16.f32 "
        "{%0,%1,%2,%3}, {%4,%5,%6,%7}, {%8,%9}, {%0,%1,%2,%3};\n"
        : "+f"(d[0]), "+f"(d[1]), "+f"(d[2]), "+f"(d[3])
        : "r"(a[0]), "r"(a[1]), "r"(a[2]), "r"(a[3]), "r"(b[0]), "r"(b[1]));
}
__device__ __forceinline__ void ldsm4(uint32_t r[4], uint32_t addr) {
    asm volatile("ldmatrix.sync.aligned.m8n8.x4.shared.b16 {%0,%1,%2,%3}, [%4];"
                 : "=r"(r[0]), "=r"(r[1]), "=r"(r[2]), "=r"(r[3]) : "r"(addr));
}
__device__ __forceinline__ uint32_t smem_u32(const void* p) {
    uint32_t a;
    asm("{ .reg .u64 t; cvta.to.shared.u64 t, %1; cvt.u32.u64 %0, t; }" : "=r"(a) : "l"(p));
    return a;
}

// ---------------------------------------------------------------
__global__ void zero_kernel() {
    int i = blockIdx.x * blockDim.x + threadIdx.x;
    if (i < Nn * Ff / 4) ((float4*)d_sum)[i] = make_float4(0.f, 0.f, 0.f, 0.f);
    if (i < Nn / 4)      ((float4*)d_cnt)[i] = make_float4(0.f, 0.f, 0.f, 0.f);
}

__global__ void prep_kernel(const float* __restrict__ W1, const float* __restrict__ b1,
                            const float* __restrict__ g1, const float* __restrict__ be1,
                            const float* __restrict__ rm1, const float* __restrict__ rv1,
                            const float* __restrict__ W2, const float* __restrict__ b2,
                            const float* __restrict__ g2, const float* __restrict__ be2,
                            const float* __restrict__ rm2, const float* __restrict__ rv2,
                            const float* __restrict__ W3) {
    int i = blockIdx.x * blockDim.x + threadIdx.x;
    if (i < 512 * 128) {
        int j = i >> 7, k = i & 127, o = j & 255;
        float s = g1[o] * rsqrtf(rv1[o] + EPS);
        float w = (j < 256) ? (W1[o * 256 + k] - W1[o * 256 + 128 + k])
                            : W1[o * 256 + 128 + k];
        d_Ch[i] = __float2half(s * w);
    }
    if (i < 256 * 256) {
        int o = i >> 8;
        float s = g2[o] * rsqrtf(rv2[o] + EPS);
        d_W2h[i] = __float2half(s * W2[i]);
    }
    if (i < 128 * 256) d_W3h[i] = __float2half(W3[i]);
    if (i < 256) {
        float s2v = g2[i] * rsqrtf(rv2[i] + EPS);
        d_b2f[i] = b2[i] * s2v + (be2[i] - rm2[i] * s2v);
    }
    if (i < 128) {
        int o0 = 2 * i, o1 = 2 * i + 1;
        float sa = g1[o0] * rsqrtf(rv1[o0] + EPS);
        float sb = g1[o1] * rsqrtf(rv1[o1] + EPS);
        d_b1h2[i] = __floats2half2_rn(b1[o0] * sa + (be1[o0] - rm1[o0] * sa),
                                      b1[o1] * sb + (be1[o1] - rm1[o1] * sb));
    }
}

// UV = x @ C^T via fp16 mma (fp32 accum; fp16 mantissa == tf32). grid (313, 2).
// Strides in half2 words; 68 % 32 == 4 -> conflict-free scalar fragment loads.
#define SXH2 68
#define UVSMEM ((64 + 256) * SXH2 * 4)
__global__ __launch_bounds__(256, 1) void uv_gemm(const float* __restrict__ x) {
    extern __shared__ __half2 smh[];
    __half2* xs2 = smh;                 // [64][SXH2]
    __half2* cs2 = smh + 64 * SXH2;     // [256][SXH2]
    const __half* xsh = (const __half*)xs2;
    const __half* csh = (const __half*)cs2;
    int t = threadIdx.x, lane = t & 31, wid = t >> 5;
    int rowBase = blockIdx.x * 64;
    int cb = blockIdx.y * 256;

    // stage x tile: fp32 -> fp16 (2048 float4 items, full 64x128)
#pragma unroll
    for (int j = 0; j < 8; ++j) {
        int idx = t + j * 256;
        int r = idx >> 5, c4 = idx & 31;
        int gr = rowBase + r;
        float4 v = (gr < Nn) ? *(const float4*)(x + (size_t)gr * 128 + c4 * 4)
                             : make_float4(0.f, 0.f, 0.f, 0.f);
        xs2[r * SXH2 + c4 * 2]     = __floats2half2_rn(v.x, v.y);
        xs2[r * SXH2 + c4 * 2 + 1] = __floats2half2_rn(v.z, v.w);
    }
    // stage C tile: 256 rows x 128 halfs = 4096 uint4 items (8 halfs each)
#pragma unroll
    for (int j = 0; j < 16; ++j) {
        int idx = t + j * 256;
        int n = idx >> 4, c8 = idx & 15;       // n: 0..255, c8: 0..15
        uint4 w = *(const uint4*)(d_Ch + (size_t)(cb + n) * 128 + c8 * 8);
        *(uint4*)((__half*)(cs2 + n * SXH2) + c8 * 8) = w;
    }
    __syncthreads();

    int warpM = wid >> 2, warpN = wid & 3;    // 2x4 warp grid
    int rB = warpM * 32, cB = warpN * 64;
    int qr = lane >> 2, qc = lane & 3;

    float acc[2][8][4] = {};
#pragma unroll
    for (int ks = 0; ks < 8; ++ks) {
        int kg = ks * 16;
        uint32_t a[2][4];
#pragma unroll
        for (int mi = 0; mi < 2; ++mi) {
            int r0 = rB + mi * 16 + qr;
            a[mi][0] = *(const uint32_t*)(xsh + r0 * (2 * SXH2) + kg + 2 * qc);
            a[mi][1] = *(const uint32_t*)(xsh + (r0 + 8) * (2 * SXH2) + kg + 2 * qc);
            a[mi][2] = *(const uint32_t*)(xsh + r0 * (2 * SXH2) + kg + 8 + 2 * qc);
            a[mi][3] = *(const uint32_t*)(xsh + (r0 + 8) * (2 * SXH2) + kg + 8 + 2 * qc);
        }
#pragma unroll
        for (int ni = 0; ni < 8; ++ni) {
            int n0 = cB + ni * 8 + qr;
            uint32_t b[2];
            b[0] = *(const uint32_t*)(csh + n0 * (2 * SXH2) + kg + 2 * qc);
            b[1] = *(const uint32_t*)(csh + n0 * (2 * SXH2) + kg + 8 + 2 * qc);
            mma16(acc[0][ni], a[0], b);
            mma16(acc[1][ni], a[1], b);
        }
    }
#pragma unroll
    for (int mi = 0; mi < 2; ++mi)
#pragma unroll
        for (int ni = 0; ni < 8; ++ni) {
            int r0 = rowBase + rB + mi * 16 + qr;
            int c0 = cb + cB + ni * 8 + 2 * qc;
            if (r0 < Nn)
                *(__half2*)(d_UVh + (size_t)r0 * 512 + c0) =
                    __floats2half2_rn(acc[mi][ni][0], acc[mi][ni][1]);
            if (r0 + 8 < Nn)
                *(__half2*)(d_UVh + (size_t)(r0 + 8) * 512 + c0) =
                    __floats2half2_rn(acc[mi][ni][2], acc[mi][ni][3]);
        }
}

// ---- persistent fused edge MLP: ldmatrix fragments, W2 resident, W3 streamed ----
// edge_index is int32 on the wire. src=ei[i], dst=ei[E+i]. Degree counting fused
// into the scatter (warpN==0 && qc==0 lanes add 1.0 per edge).
__global__ __launch_bounds__(THREADS, 1) void edge_kernel(const int* __restrict__ ei,
                                                          const float* __restrict__ b3) {
    extern __shared__ char smem[];
    uint32_t sb = smem_u32(smem);
    int t = threadIdx.x, lane = t & 31, wid = t >> 5;

    // ---- load W2 into 4 swizzled panels (once per CTA) ----
#pragma unroll
    for (int j = 0; j < 16; ++j) {
        int item = j * THREADS + t;              // 8192 items
        int r = item >> 5, p = (item >> 3) & 3, ch = item & 7;
        uint4 w = *(const uint4*)(d_W2h + (size_t)r * 256 + p * 64 + ch * 8);
        *(uint4*)(smem + OFF_W2 + p * 32768 + SWZ(r * 128 + ch * 16)) = w;
    }

    int warpM = wid >> 2, warpN = wid & 3;       // 4x4 warp grid
    int qr = lane >> 2, qc = lane & 3;
    uint32_t xorl = (uint32_t)(lane & 7) << 4;   // SW128 XOR for ldmatrix rows (row%8 == lane&7)
    uint32_t xorq = (uint32_t)qr << 4;           // SW128 XOR for epilogue rows (row%8 == qr)
    const __half2 z2 = __float2half2_rn(0.f);

    // ldmatrix per-lane bases
    uint32_t aColHi = ((lane >> 4) & 1) * 16;
    uint32_t aBase  = sb + OFF_H1 + (warpM * 32 + (lane & 15)) * 128;
    uint32_t bRowOff = (uint32_t)((lane & 7) + ((lane >> 4) << 3));
    uint32_t bColHi  = ((lane >> 3) & 1) * 16;
    uint32_t b2Base  = sb + OFF_W2 + (warpN * 64 + bRowOff) * 128;
    uint32_t b3Base  = sb + OFF_W3 + (warpN * 32 + bRowOff) * 128;

    // W3 chunk-stream item coords (per thread, 2 items of 16B per chunk)
    int w3n0 = t >> 3, w3ch = t & 7;
    int w3n1 = (512 + t) >> 3;
    uint32_t w3soff0 = SWZ(w3n0 * 128 + w3ch * 16);
    uint32_t w3soff1 = SWZ(w3n1 * 128 + w3ch * 16);

    for (int tile = blockIdx.x; tile < TILES; tile += gridDim.x) {
        int e0 = tile * EPB;
        __syncthreads();   // h1 free: prev tile's layer-3 reads done

        // ---- gather + layer-1 -> h1 panels (fp16, swizzled), 128 edges ----
#pragma unroll
        for (int j = 0; j < 8; ++j) {
            int item = j * THREADS + t;          // 4096 items
            int e = item >> 5, p = (item >> 3) & 3, ch = item & 7;
            int sidx = __ldg(ei + e0 + e);
            int didx = __ldg(ei + Ee + e0 + e);
            uint4 uu = *(const uint4*)(d_UVh + (size_t)didx * 512 + p * 64 + ch * 8);
            uint4 vv = *(const uint4*)(d_UVh + (size_t)sidx * 512 + 256 + p * 64 + ch * 8);
            const __half2* up = (const __half2*)&uu;
            const __half2* vp = (const __half2*)&vv;
            __half2 r[4];
#pragma unroll
            for (int q = 0; q < 4; ++q)
                r[q] = __hmax2(__hadd2(__hadd2(up[q], vp[q]), d_b1h2[p * 32 + ch * 4 + q]), z2);
            *(uint4*)(smem + OFF_H1 + p * 16384 + SWZ(e * 128 + ch * 16)) = *(uint4*)r;
        }
        __syncthreads();

        // ---- layer 2: [128,256] = h1 @ W2^T, warp tile 32x64, ldmatrix frags ----
        float acc[2][8][4] = {};
        {
#pragma unroll
            for (int ks = 0; ks < 16; ++ks) {
                int kg = ks * 16, p = kg >> 6;
                uint32_t kp2 = (uint32_t)((kg & 63) * 2);
                uint32_t a0[4], a1[4];
                uint32_t acb = (kp2 + aColHi) ^ xorl;
                ldsm4(a0, aBase + p * 16384 + acb);
                ldsm4(a1, aBase + 2048 + p * 16384 + acb);
                uint32_t wb = b2Base + p * 32768 + ((kp2 + bColHi) ^ xorl);
#pragma unroll
                for (int ni2 = 0; ni2 < 4; ++ni2) {
                    uint32_t bb[4];
                    ldsm4(bb, wb + ni2 * 2048);
                    mma16(acc[0][2 * ni2],     a0, bb);
                    mma16(acc[1][2 * ni2],     a1, bb);
                    mma16(acc[0][2 * ni2 + 1], a0, bb + 2);
                    mma16(acc[1][2 * ni2 + 1], a1, bb + 2);
                }
            }
        }

        // prefetch W3 chunks 0,1 (LDG into regs; STS after sync)
        uint4 wA0 = *(const uint4*)(d_W3h + (size_t)w3n0 * 256 + 0 * 64 + w3ch * 8);
        uint4 wA1 = *(const uint4*)(d_W3h + (size_t)w3n1 * 256 + 0 * 64 + w3ch * 8);
        uint4 wB0 = *(const uint4*)(d_W3h + (size_t)w3n0 * 256 + 1 * 64 + w3ch * 8);
        uint4 wB1 = *(const uint4*)(d_W3h + (size_t)w3n1 * 256 + 1 * 64 + w3ch * 8);

        __syncthreads();   // all layer-2 reads of h1 done

        // ---- bias + relu + fp16: h2 over h1 panels; stage W3 chunks 0,1 ----
        {
            int rB = warpM * 32, cB = warpN * 64;
#pragma unroll
            for (int mi = 0; mi < 2; ++mi) {
                int r0 = rB + mi * 16 + qr, r1 = r0 + 8;
#pragma unroll
                for (int ni = 0; ni < 8; ++ni) {
                    int c0 = cB + ni * 8 + 2 * qc;
                    int p = c0 >> 6, cp = c0 & 63;
                    float2 bb = __ldg((const float2*)(d_b2f + c0));
                    char* hp = smem + OFF_H1 + p * 16384;
                    uint32_t coff = ((uint32_t)(cp * 2)) ^ xorq;   // row%8 == qr here
                    *(__half2*)(hp + r0 * 128 + coff) =
                        __floats2half2_rn(fmaxf(acc[mi][ni][0] + bb.x, 0.f),
                                          fmaxf(acc[mi][ni][1] + bb.y, 0.f));
                    *(__half2*)(hp + r1 * 128 + coff) =
                        __floats2half2_rn(fmaxf(acc[mi][ni][2] + bb.x, 0.f),
                                          fmaxf(acc[mi][ni][3] + bb.y, 0.f));
                }
            }
            *(uint4*)(smem + OFF_W3 + w3soff0) = wA0;
            *(uint4*)(smem + OFF_W3 + w3soff1) = wA1;
            *(uint4*)(smem + OFF_W3 + 16384 + w3soff0) = wB0;
            *(uint4*)(smem + OFF_W3 + 16384 + w3soff1) = wB1;
        }
        // prefetch W3 chunks 2,3
        wA0 = *(const uint4*)(d_W3h + (size_t)w3n0 * 256 + 2 * 64 + w3ch * 8);
        wA1 = *(const uint4*)(d_W3h + (size_t)w3n1 * 256 + 2 * 64 + w3ch * 8);
        wB0 = *(const uint4*)(d_W3h + (size_t)w3n0 * 256 + 3 * 64 + w3ch * 8);
        wB1 = *(const uint4*)(d_W3h + (size_t)w3n1 * 256 + 3 * 64 + w3ch * 8);

        __syncthreads();   // h2 + W3 chunks 0,1 visible

        // ---- layer 3: [128,128] = h2 @ W3^T, warp tile 32x32, ldmatrix frags ----
        float acc3[2][4][4] = {};
#pragma unroll
        for (int kc = 0; kc < 2; ++kc) {
            uint32_t wb3 = b3Base + kc * 16384;
            uint32_t ab3 = aBase + kc * 16384;          // A panel = kc
#pragma unroll
            for (int ks = 0; ks < 4; ++ks) {
                uint32_t kp2 = (uint32_t)(ks * 32);
                uint32_t a0[4], a1[4];
                uint32_t acb = (kp2 + aColHi) ^ xorl;
                ldsm4(a0, ab3 + acb);
                ldsm4(a1, ab3 + 2048 + acb);
                uint32_t wb = wb3 + ((kp2 + bColHi) ^ xorl);
#pragma unroll
                for (int ni2 = 0; ni2 < 2; ++ni2) {
                    uint32_t bb[4];
                    ldsm4(bb, wb + ni2 * 2048);
                    mma16(acc3[0][2 * ni2],     a0, bb);
                    mma16(acc3[1][2 * ni2],     a1, bb);
                    mma16(acc3[0][2 * ni2 + 1], a0, bb + 2);
                    mma16(acc3[1][2 * ni2 + 1], a1, bb + 2);
                }
            }
        }
        __syncthreads();   // chunk buffers 0,1 consumed
        *(uint4*)(smem + OFF_W3 + w3soff0) = wA0;
        *(uint4*)(smem + OFF_W3 + w3soff1) = wA1;
        *(uint4*)(smem + OFF_W3 + 16384 + w3soff0) = wB0;
        *(uint4*)(smem + OFF_W3 + 16384 + w3soff1) = wB1;
        __syncthreads();   // chunks 2,3 staged
#pragma unroll
        for (int kc = 0; kc < 2; ++kc) {
            uint32_t wb3 = b3Base + kc * 16384;
            uint32_t ab3 = aBase + (2 + kc) * 16384;    // A panel = 2+kc
#pragma unroll
            for (int ks = 0; ks < 4; ++ks) {
                uint32_t kp2 = (uint32_t)(ks * 32);
                uint32_t a0[4], a1[4];
                uint32_t acb = (kp2 + aColHi) ^ xorl;
                ldsm4(a0, ab3 + acb);
                ldsm4(a1, ab3 + 2048 + acb);
                uint32_t wb = wb3 + ((kp2 + bColHi) ^ xorl);
#pragma unroll
                for (int ni2 = 0; ni2 < 2; ++ni2) {
                    uint32_t bb[4];
                    ldsm4(bb, wb + ni2 * 2048);
                    mma16(acc3[0][2 * ni2],     a0, bb);
                    mma16(acc3[1][2 * ni2],     a1, bb);
                    mma16(acc3[0][2 * ni2 + 1], a0, bb + 2);
                    mma16(acc3[1][2 * ni2 + 1], a1, bb + 2);
                }
            }
        }

        // ---- scatter: bias + vector atomics into d_sum[dst]; fused degree count ----
        int rB = warpM * 32, cB3 = warpN * 32;
#pragma unroll
        for (int mi = 0; mi < 2; ++mi) {
            int r0 = rB + mi * 16 + qr;
            int d0 = __ldg(ei + Ee + e0 + r0);
            int d1 = __ldg(ei + Ee + e0 + r0 + 8);
            float* p0b = d_sum + (size_t)d0 * Ff;
            float* p1b = d_sum + (size_t)d1 * Ff;
            if (warpN == 0 && qc == 0) {
                asm volatile("red.global.add.f32 [%0], %1;" :: "l"(d_cnt + d0), "f"(1.0f) : "memory");
                asm volatile("red.global.add.f32 [%0], %1;" :: "l"(d_cnt + d1), "f"(1.0f) : "memory");
            }
#pragma unroll
            for (int ni = 0; ni < 4; ++ni) {
                int c0 = cB3 + ni * 8 + 2 * qc;
                float2 bb = __ldg((const float2*)(b3 + c0));
                asm volatile("red.global.add.v2.f32 [%0], {%1,%2};"
                             :: "l"(p0b + c0), "f"(acc3[mi][ni][0] + bb.x),
                                "f"(acc3[mi][ni][1] + bb.y) : "memory");
                asm volatile("red.global.add.v2.f32 [%0], {%1,%2};"
                             :: "l"(p1b + c0), "f"(acc3[mi][ni][2] + bb.x),
                                "f"(acc3[mi][ni][3] + bb.y) : "memory");
            }
        }
    }
}

__global__ void final_kernel(float* __restrict__ out) {
    int i = blockIdx.x * blockDim.x + threadIdx.x;
    if (i < Nn * Ff / 4) {
        int n = i >> 5;                       // (i*4) >> 7
        float c = fmaxf(d_cnt[n], 1.0f);
        float4 v = ((const float4*)d_sum)[i];
        ((float4*)out)[i] = make_float4(tanhf(v.x / c), tanhf(v.y / c),
                                        tanhf(v.z / c), tanhf(v.w / c));
    }
}

// ---------------------------------------------------------------
extern "C" void kernel_launch(void* const* d_in, const int* in_sizes, int n_in,
                              void* d_out, int out_size) {
    const float* x  = (const float*)d_in[0];
    const int*   ei = (const int*)d_in[1];     // int32 (JAX x64 disabled)
    const float* W1 = (const float*)d_in[2];
    const float* b1 = (const float*)d_in[3];
    const float* g1 = (const float*)d_in[4];
    const float* be1 = (const float*)d_in[5];
    const float* rm1 = (const float*)d_in[6];
    const float* rv1 = (const float*)d_in[7];
    const float* W2 = (const float*)d_in[8];
    const float* b2 = (const float*)d_in[9];
    const float* g2 = (const float*)d_in[10];
    const float* be2 = (const float*)d_in[11];
    const float* rm2 = (const float*)d_in[12];
    const float* rv2 = (const float*)d_in[13];
    const float* W3 = (const float*)d_in[14];
    const float* b3 = (const float*)d_in[15];
    float* out = (float*)d_out;

    cudaFuncSetAttribute(uv_gemm, cudaFuncAttributeMaxDynamicSharedMemorySize, UVSMEM);
    cudaFuncSetAttribute(edge_kernel, cudaFuncAttributeMaxDynamicSharedMemorySize, EDGESMEM);

    zero_kernel<<<(Nn * Ff / 4 + 255) / 256, 256>>>();
    prep_kernel<<<(512 * 128 + 255) / 256, 256>>>(W1, b1, g1, be1, rm1, rv1,
                                                  W2, b2, g2, be2, rm2, rv2, W3);
    uv_gemm<<<dim3((Nn + 63) / 64, 2), 256, UVSMEM>>>(x);
    edge_kernel<<<EDGE_GRID, THREADS, EDGESMEM>>>(ei, b3);
    final_kernel<<<(Nn * Ff / 4 + 255) / 256, 256>>>(out);
}